// round 1
// baseline (speedup 1.0000x reference)
#include <cuda_runtime.h>
#include <math.h>

// ---- problem constants ----
#define Bb 64
#define Nn 256
#define Tt 96
#define Pp 8
#define Ss 4
#define Dd 128
#define Hh 8
#define DHd 16
#define Kk 16
#define PLl 24
#define Ll 23          // num patches
#define LPAD 24        // padded for float4

// ---- scratch (static device globals; no allocation allowed) ----
__device__ float g_maskf[Bb*Nn];
__device__ int   g_mode;
__device__ float g_hzero[Dd];
__device__ float g_hmean[Bb*Nn*Dd];
__device__ int   g_obsidx[Bb*Nn];
__device__ int   g_nobs[Bb];
__device__ float g_tokens[Bb*Nn*Dd];
__device__ float g_q[Bb*Nn*Dd];
__device__ float g_k[Bb*Nn*Dd];
__device__ float g_v[Bb*Nn*Dd];
__device__ float g_attnv[Bb*Nn*Dd];
__device__ float g_afill[Bb*Dd];

__device__ __forceinline__ float gelu_tanh(float x){
    // jax.nn.gelu default (approximate=True)
    float x3 = x*x*x;
    return 0.5f*x*(1.0f + tanhf(0.7978845608028654f*(x + 0.044715f*x3)));
}

// ---- mask dtype sniffer: 0=float32, 1=int32, 2=byte/bool ----
__global__ void kdetect(const unsigned char* __restrict__ mp){
    __shared__ int sawF, sawB;
    if (threadIdx.x == 0){ sawF = 0; sawB = 0; }
    __syncthreads();
    for (int i = threadIdx.x; i < Bb*Nn; i += blockDim.x){
        unsigned char c = mp[i];
        if (c == 0x3f || c == 0x80) sawF = 1;
        else if (c != 0 && (i & 3) != 0) sawB = 1;
    }
    __syncthreads();
    if (threadIdx.x == 0) g_mode = sawF ? 0 : (sawB ? 2 : 1);
}

__global__ void kdecode(const void* __restrict__ mp){
    int i = blockIdx.x*blockDim.x + threadIdx.x;
    if (i >= Bb*Nn) return;
    int mode = g_mode;
    bool m;
    if (mode == 0)      m = ((const float*)mp)[i] != 0.0f;
    else if (mode == 1) m = ((const int*)mp)[i]   != 0;
    else                m = ((const unsigned char*)mp)[i] != 0;
    g_maskf[i] = m ? 1.0f : 0.0f;
}

// ---- h for an all-zero (unobserved) variate: h_zero = bp + gelu(bp@W1)@W2 ----
__global__ void khzero(const float* __restrict__ bp,
                       const float* __restrict__ W1,
                       const float* __restrict__ W2){
    __shared__ float sh0[Dd];
    __shared__ float sg[2*Dd];
    int tid = threadIdx.x;
    if (tid < Dd) sh0[tid] = bp[tid];
    __syncthreads();
    float u = 0.f;
    #pragma unroll 4
    for (int d = 0; d < Dd; d++) u += sh0[d]*W1[d*256 + tid];
    sg[tid] = gelu_tanh(u);
    __syncthreads();
    if (tid < Dd){
        float v = 0.f;
        #pragma unroll 4
        for (int j = 0; j < 2*Dd; j++) v += sg[j]*W2[j*Dd + tid];
        g_hzero[tid] = sh0[tid] + v;
    }
}

// ---- stage 1: h_mean[b,n,:] = mean_l (h0_l + gelu(h0_l@W1)@W2) ----
// Uses: sum_l gelu(u_l)@W2 = (sum_l gelu(u_l))@W2  -> single matvec per (b,n)
__global__ __launch_bounds__(256) void kstage1(
    const float* __restrict__ x,
    const float* __restrict__ Wp,
    const float* __restrict__ bp,
    const float* __restrict__ W1,
    const float* __restrict__ W2){
    int bn = blockIdx.x;
    int tid = threadIdx.x;
    if (g_maskf[bn] == 0.0f){
        if (tid < Dd) g_hmean[bn*Dd + tid] = g_hzero[tid];
        return;
    }
    __shared__ float sx[Tt];
    __shared__ float sh0[Dd*LPAD];   // [d][l], l-padded to 24 (float4)
    __shared__ float sG[2*Dd];
    __shared__ float sv[Dd];

    if (tid < Tt) sx[tid] = x[bn*Tt + tid];
    __syncthreads();

    // phase A: per-patch embeddings h0[d][l]
    for (int idx = tid; idx < Dd*Ll; idx += 256){
        int d = idx & (Dd-1);
        int l = idx >> 7;
        float a = bp[d];
        #pragma unroll
        for (int p = 0; p < Pp; p++) a += sx[l*Ss + p]*Wp[p*Dd + d];
        sh0[d*LPAD + l] = a;
    }
    if (tid < Dd) sh0[tid*LPAD + Ll] = 0.0f;   // pad lane
    __syncthreads();

    // phase B: u[l][j] for j=tid; accumulate over d with one W1 load per d
    float u[LPAD];
    #pragma unroll
    for (int l = 0; l < LPAD; l++) u[l] = 0.0f;
    int j = tid;
    #pragma unroll 2
    for (int d = 0; d < Dd; d++){
        float w = W1[d*256 + j];
        const float4* row = (const float4*)(sh0 + d*LPAD);
        #pragma unroll
        for (int c4 = 0; c4 < LPAD/4; c4++){
            float4 hv = row[c4];
            u[c4*4+0] += hv.x*w;
            u[c4*4+1] += hv.y*w;
            u[c4*4+2] += hv.z*w;
            u[c4*4+3] += hv.w*w;
        }
    }
    float G = 0.f;
    #pragma unroll
    for (int l = 0; l < Ll; l++) G += gelu_tanh(u[l]);
    sG[j] = G;
    __syncthreads();

    // phase C: vsum[d] = sum_j G[j]*W2[j][d]; split j-range over thread halves
    int d = tid & (Dd-1);
    int half = tid >> 7;
    float vt = 0.f;
    int j0 = half*Dd;
    #pragma unroll 4
    for (int jj = 0; jj < Dd; jj++) vt += sG[j0+jj]*W2[(j0+jj)*Dd + d];
    if (half) sv[d] = vt;
    __syncthreads();
    if (!half){
        float h0s = 0.f;
        #pragma unroll
        for (int l = 0; l < Ll; l++) h0s += sh0[d*LPAD + l];
        g_hmean[bn*Dd + d] = (h0s + vt + sv[d]) * (1.0f/23.0f);
    }
}

// ---- per-batch stable compaction (observed first, original order) ----
__global__ void kscan(){
    __shared__ int s[Nn];
    int b = blockIdx.x, tid = threadIdx.x;
    int m = (g_maskf[b*Nn + tid] > 0.0f) ? 1 : 0;
    s[tid] = m;
    __syncthreads();
    for (int off = 1; off < Nn; off <<= 1){
        int t = (tid >= off) ? s[tid-off] : 0;
        __syncthreads();
        s[tid] += t;
        __syncthreads();
    }
    int incl = s[tid];
    int total = s[Nn-1];
    int rank = incl - m;
    int pos = m ? rank : (total + tid - rank);
    g_obsidx[b*Nn + pos] = tid;
    if (tid == 0) g_nobs[b] = total;
}

// ---- tokens[b,i,:] = h_mean[b,obs_idx[i],:] + var_embed[obs_idx[i],:] ----
__global__ void ktokens(const float* __restrict__ var_embed){
    int bn = blockIdx.x;
    int b = bn >> 8, i = bn & 255;
    int tid = threadIdx.x;
    float val = 0.f;
    if (i < g_nobs[b]){
        int src = g_obsidx[b*Nn + i];
        val = g_hmean[(b*Nn + src)*Dd + tid] + var_embed[src*Dd + tid];
    }
    g_tokens[bn*Dd + tid] = val;
}

// ---- q/k/v projections for valid tokens ----
__global__ __launch_bounds__(384) void kqkv(
    const float* __restrict__ Wq,
    const float* __restrict__ Wk,
    const float* __restrict__ Wv){
    int bn = blockIdx.x;
    int b = bn >> 8, i = bn & 255;
    if (i >= g_nobs[b]) return;
    __shared__ float tok[Dd];
    int tid = threadIdx.x;
    if (tid < Dd) tok[tid] = g_tokens[bn*Dd + tid];
    __syncthreads();
    int which = tid / Dd, c = tid & (Dd-1);
    const float* W = (which == 0) ? Wq : (which == 1 ? Wk : Wv);
    float a = 0.f;
    #pragma unroll 4
    for (int d = 0; d < Dd; d++) a += tok[d]*W[d*Dd + c];
    float* dst = (which == 0) ? g_q : (which == 1 ? g_k : g_v);
    dst[bn*Dd + c] = a;
}

// ---- attention per (b,h): softmax over valid keys only ----
__global__ __launch_bounds__(256) void kattn(){
    __shared__ float ks[Nn*17];
    __shared__ float vs[Nn*16];
    __shared__ float qs[8][16];
    __shared__ float pr[8][Nn];
    int b = blockIdx.x / Hh, h = blockIdx.x % Hh;
    int n = g_nobs[b];
    int tid = threadIdx.x;
    for (int idx = tid; idx < n*16; idx += 256){
        int jj = idx >> 4, c = idx & 15;
        ks[jj*17 + c] = g_k[(b*Nn + jj)*Dd + h*16 + c];
        vs[jj*16 + c] = g_v[(b*Nn + jj)*Dd + h*16 + c];
    }
    __syncthreads();
    int w = tid >> 5, lane = tid & 31;
    for (int i = w; i < n; i += 8){
        if (lane < 16) qs[w][lane] = g_q[(b*Nn + i)*Dd + h*16 + lane];
        __syncwarp();
        float sc[8];
        float mx = -1e30f;
        #pragma unroll
        for (int r = 0; r < 8; r++){
            int jj = lane + 32*r;
            float s = -1e30f;
            if (jj < n){
                s = 0.f;
                #pragma unroll
                for (int c = 0; c < 16; c++) s += qs[w][c]*ks[jj*17 + c];
                s *= 0.25f;  // dh^-0.5
            }
            sc[r] = s;
            mx = fmaxf(mx, s);
        }
        #pragma unroll
        for (int off = 16; off; off >>= 1) mx = fmaxf(mx, __shfl_xor_sync(0xffffffffu, mx, off));
        float se = 0.f;
        #pragma unroll
        for (int r = 0; r < 8; r++){
            int jj = lane + 32*r;
            float p = (jj < n) ? expf(sc[r] - mx) : 0.f;
            sc[r] = p; se += p;
        }
        #pragma unroll
        for (int off = 16; off; off >>= 1) se += __shfl_xor_sync(0xffffffffu, se, off);
        float inv = 1.0f/se;
        #pragma unroll
        for (int r = 0; r < 8; r++){
            int jj = lane + 32*r;
            if (jj < n) pr[w][jj] = sc[r]*inv;
        }
        __syncwarp();
        int c = lane & 15, hh = lane >> 4;
        float acc = 0.f;
        for (int jj = hh; jj < n; jj += 2) acc += pr[w][jj]*vs[jj*16 + c];
        acc += __shfl_xor_sync(0xffffffffu, acc, 16);
        if (hh == 0) g_attnv[(b*Nn + i)*Dd + h*16 + c] = acc;
        __syncwarp();
    }
}

// ---- per-batch epilogue: Q_sub, w_sub, confidence, alpha*fill ----
__global__ __launch_bounds__(128) void kfinal(
    const float* __restrict__ Wo,
    const float* __restrict__ C,
    const float* __restrict__ Wdec,
    float* __restrict__ outQ,
    float* __restrict__ outW,
    float* __restrict__ outC){
    __shared__ float sa[Dd], Qs[Dd], lg[Kk], wk[Kk], zc[Dd];
    __shared__ float s_alpha, s_conf;
    int b = blockIdx.x, d = threadIdx.x;
    int n = g_nobs[b];
    float a = 0.f, t = 0.f;
    for (int i = 0; i < n; i++){
        a += g_attnv[(b*Nn + i)*Dd + d];
        t += g_tokens[(b*Nn + i)*Dd + d];
    }
    sa[d] = a;
    __syncthreads();
    float q = 0.f;
    #pragma unroll 4
    for (int jj = 0; jj < Dd; jj++) q += sa[jj]*Wo[jj*Dd + d];
    q = (q + t)/(float)n;
    Qs[d] = q;
    __syncthreads();
    if (d < Kk){
        float lgv = 0.f;
        #pragma unroll 4
        for (int dd = 0; dd < Dd; dd++) lgv += Qs[dd]*C[d*Dd + dd];
        lg[d] = lgv * 2.0f;  // / TAU
    }
    __syncthreads();
    if (d == 0){
        float mx = -1e30f;
        for (int k = 0; k < Kk; k++) mx = fmaxf(mx, lg[k]);
        float s = 0.f;
        for (int k = 0; k < Kk; k++){ wk[k] = expf(lg[k]-mx); s += wk[k]; }
        float inv = 1.0f/s, wmax = 0.f;
        for (int k = 0; k < Kk; k++){ wk[k] *= inv; wmax = fmaxf(wmax, wk[k]); }
        float conf = wmax * ((float)n/(float)Nn);
        s_conf = conf;
        s_alpha = 0.1f + 0.9f*conf;
    }
    __syncthreads();
    float z = 0.f;
    #pragma unroll
    for (int k = 0; k < Kk; k++) z += wk[k]*C[k*Dd + d];
    zc[d] = z;
    __syncthreads();
    float f = 0.f;
    #pragma unroll 4
    for (int jj = 0; jj < Dd; jj++) f += zc[jj]*Wdec[jj*Dd + d];
    g_afill[b*Dd + d] = s_alpha * f;
    if (outQ) outQ[b*Dd + d] = q;
    if (outW && d < Kk) outW[b*Kk + d] = wk[d];
    if (outC && d == 0) outC[b] = s_conf;
}

// ---- y_hat = (h_mean + alpha*(1-m)*fill) @ W_head ----
__global__ __launch_bounds__(128) void kyhat(
    const float* __restrict__ Wh,
    float* __restrict__ y){
    __shared__ float E[Dd];
    int bn = blockIdx.x;
    int b = bn >> 8;
    int tid = threadIdx.x;
    float m = g_maskf[bn];
    E[tid] = g_hmean[bn*Dd + tid] + (1.0f - m)*g_afill[b*Dd + tid];
    __syncthreads();
    if (tid < PLl){
        float acc = 0.f;
        #pragma unroll 4
        for (int d = 0; d < Dd; d++) acc += E[d]*Wh[d*PLl + tid];
        y[bn*PLl + tid] = acc;
    }
}

extern "C" void kernel_launch(void* const* d_in, const int* in_sizes, int n_in,
                              void* d_out, int out_size){
    const float* x    = (const float*)d_in[0];
    const void*  mask = d_in[1];
    const float* Wp   = (const float*)d_in[2];
    const float* bp   = (const float*)d_in[3];
    const float* W1   = (const float*)d_in[4];
    const float* W2   = (const float*)d_in[5];
    const float* ve   = (const float*)d_in[6];
    const float* Wq   = (const float*)d_in[7];
    const float* Wk   = (const float*)d_in[8];
    const float* Wv   = (const float*)d_in[9];
    const float* Wo   = (const float*)d_in[10];
    const float* C    = (const float*)d_in[11];
    const float* Wdec = (const float*)d_in[12];
    const float* Wh   = (const float*)d_in[13];

    float* out = (float*)d_out;
    const int SZ_Y = Bb*Nn*PLl;          // 393216
    const int SZ_Q = Bb*Dd;              // 8192
    const int SZ_W = Bb*Kk;              // 1024
    float* oy = out;
    float* oq = (out_size >= SZ_Y + SZ_Q)              ? out + SZ_Y            : nullptr;
    float* ow = (out_size >= SZ_Y + SZ_Q + SZ_W)       ? out + SZ_Y + SZ_Q     : nullptr;
    float* oc = (out_size >= SZ_Y + SZ_Q + SZ_W + Bb)  ? out + SZ_Y + SZ_Q + SZ_W : nullptr;

    kdetect<<<1, 256>>>((const unsigned char*)mask);
    kdecode<<<(Bb*Nn + 255)/256, 256>>>(mask);
    khzero<<<1, 256>>>(bp, W1, W2);
    kstage1<<<Bb*Nn, 256>>>(x, Wp, bp, W1, W2);
    kscan<<<Bb, Nn>>>();
    ktokens<<<Bb*Nn, Dd>>>(ve);
    kqkv<<<Bb*Nn, 3*Dd>>>(Wq, Wk, Wv);
    kattn<<<Bb*Hh, 256>>>();
    kfinal<<<Bb, Dd>>>(Wo, C, Wdec, oq, ow, oc);
    kyhat<<<Bb*Nn, Dd>>>(Wh, oy);
}

// round 2
// speedup vs baseline: 2.4623x; 2.4623x over previous
#include <cuda_runtime.h>
#include <math.h>

// ---- problem constants ----
#define Bb 64
#define Nn 256
#define Tt 96
#define Pp 8
#define Ss 4
#define Dd 128
#define Hh 8
#define Kk 16
#define PLl 24
#define Ll 23

// ---- scratch ----
__device__ float g_maskf[Bb*Nn];
__device__ int   g_mode;
__device__ float g_wf[9*256];          // rows 0..7: (Wp@W1)[p][j]; row 8: bp@W1
__device__ float g_hmean[Bb*Nn*Dd];
__device__ int   g_obsidx[Bb*Nn];
__device__ int   g_nobs[Bb];
__device__ float g_tokens[Bb*Nn*Dd];
__device__ float g_q[Bb*Nn*Dd];
__device__ float g_k[Bb*Nn*Dd];
__device__ float g_v[Bb*Nn*Dd];
__device__ float g_attnv[Bb*Nn*Dd];
__device__ float g_afill[Bb*Dd];

#define FMA2(d,a,b,c) asm("fma.rn.f32x2 %0, %1, %2, %3;" : "=l"(d) : "l"(a), "l"(b), "l"(c))
#define PACKF2(o,f)   asm("mov.b64 %0, {%1, %1};" : "=l"(o) : "r"(__float_as_uint(f)))

__device__ __forceinline__ float gelu_fast(float x){
    // 0.5x(1+tanh(z)), z = 0.79788456*(x+0.044715 x^3); tanh(z) = 1 - 2/(e^{2z}+1)
    float x3 = x*x*x;
    float y  = 1.5957691216057308f*(x + 0.044715f*x3);   // 2z
    float e  = __expf(y);
    return x - __fdividef(x, e + 1.0f);
}

// ---- mask dtype sniffer: 0=float32, 1=int32, 2=byte/bool ----
__global__ void kdetect(const unsigned char* __restrict__ mp){
    __shared__ int sawF, sawB;
    if (threadIdx.x == 0){ sawF = 0; sawB = 0; }
    __syncthreads();
    for (int i = threadIdx.x; i < Bb*Nn; i += blockDim.x){
        unsigned char c = mp[i];
        if (c == 0x3f || c == 0x80) sawF = 1;
        else if (c != 0 && (i & 3) != 0) sawB = 1;
    }
    __syncthreads();
    if (threadIdx.x == 0) g_mode = sawF ? 0 : (sawB ? 2 : 1);
}

__global__ void kdecode(const void* __restrict__ mp){
    int i = blockIdx.x*blockDim.x + threadIdx.x;
    if (i >= Bb*Nn) return;
    int mode = g_mode;
    bool m;
    if (mode == 0)      m = ((const float*)mp)[i] != 0.0f;
    else if (mode == 1) m = ((const int*)mp)[i]   != 0;
    else                m = ((const unsigned char*)mp)[i] != 0;
    g_maskf[i] = m ? 1.0f : 0.0f;
}

// ---- fold patch-embed into W1: Wf[p][j] = sum_d Wp[p][d] W1[d][j]; row8 = bp@W1 ----
__global__ __launch_bounds__(256) void kprep(const float* __restrict__ Wp,
                                             const float* __restrict__ bp,
                                             const float* __restrict__ W1){
    __shared__ float sWp[Pp*Dd];
    __shared__ float sbp[Dd];
    int tid = threadIdx.x;
    for (int i = tid; i < Pp*Dd; i += 256) sWp[i] = Wp[i];
    if (tid < Dd) sbp[tid] = bp[tid];
    __syncthreads();
    int j = tid;
    float acc[9];
    #pragma unroll
    for (int p = 0; p < 9; p++) acc[p] = 0.f;
    for (int d = 0; d < Dd; d++){
        float w1 = W1[d*256 + j];
        #pragma unroll
        for (int p = 0; p < Pp; p++) acc[p] += sWp[p*Dd + d]*w1;
        acc[8] += sbp[d]*w1;
    }
    #pragma unroll
    for (int p = 0; p < 9; p++) g_wf[p*256 + j] = acc[p];
}

// ---- stage 1: h_mean for 8 tokens per block ----
__global__ __launch_bounds__(256) void kstage1(
    const float* __restrict__ x,
    const float* __restrict__ Wp,
    const float* __restrict__ bp,
    const float* __restrict__ W2){
    __shared__ float sx[8][Tt];       // masked x, [t][c]
    __shared__ float sxs[8][Pp];      // per-token column sums
    __shared__ float sGT[256*8];      // [j][t]
    __shared__ float sv[8][Dd];       // phase-C partial
    int tid = threadIdx.x;
    int bn0 = blockIdx.x*8;

    for (int idx = tid; idx < 8*Tt; idx += 256){
        int t = idx/Tt, c = idx - t*Tt;
        sx[t][c] = x[(bn0+t)*Tt + c] * g_maskf[bn0+t];
    }
    __syncthreads();
    if (tid < 64){
        int t = tid >> 3, p = tid & 7;
        float s = 0.f;
        #pragma unroll
        for (int l = 0; l < Ll; l++) s += sx[t][l*Ss + p];
        sxs[t][p] = s;
    }

    // phase B: G[t][j] = sum_l gelu(ubias[j] + x_patch_l . Wf[:,j])
    {
        int j = tid;
        float wf[8];
        #pragma unroll
        for (int p = 0; p < 8; p++) wf[p] = g_wf[p*256 + j];
        float ub = g_wf[8*256 + j];
        #pragma unroll 1
        for (int t = 0; t < 8; t++){
            const float4* xv = (const float4*)sx[t];
            float4 a = xv[0];
            float g = 0.f;
            #pragma unroll
            for (int l = 0; l < Ll; l++){
                float4 b2 = xv[l+1];
                float u = ub + a.x*wf[0] + a.y*wf[1] + a.z*wf[2] + a.w*wf[3]
                             + b2.x*wf[4] + b2.y*wf[5] + b2.z*wf[6] + b2.w*wf[7];
                g += gelu_fast(u);
                a = b2;
            }
            sGT[j*8 + t] = g;
        }
    }
    __syncthreads();

    // phase C: hm[t][d] = (23*bp[d] + xs.Wp[:,d] + sum_j G[t][j] W2[j][d]) / 23
    {
        int d = tid & 127, h2 = tid >> 7;
        float acc[8];
        #pragma unroll
        for (int t = 0; t < 8; t++) acc[t] = 0.f;
        int j0 = h2*128;
        for (int j = j0; j < j0+128; j++){
            float4 ga = *(const float4*)&sGT[j*8];
            float4 gb = *(const float4*)&sGT[j*8+4];
            float w = W2[j*Dd + d];
            acc[0] += ga.x*w; acc[1] += ga.y*w; acc[2] += ga.z*w; acc[3] += ga.w*w;
            acc[4] += gb.x*w; acc[5] += gb.y*w; acc[6] += gb.z*w; acc[7] += gb.w*w;
        }
        if (h2){
            #pragma unroll
            for (int t = 0; t < 8; t++) sv[t][d] = acc[t];
        }
        __syncthreads();
        if (!h2){
            float bpd = bp[d];
            float wpc[8];
            #pragma unroll
            for (int p = 0; p < 8; p++) wpc[p] = Wp[p*Dd + d];
            #pragma unroll
            for (int t = 0; t < 8; t++){
                float hs = 23.0f*bpd;
                #pragma unroll
                for (int p = 0; p < 8; p++) hs += sxs[t][p]*wpc[p];
                g_hmean[(bn0+t)*Dd + d] = (hs + acc[t] + sv[t][d]) * (1.0f/23.0f);
            }
        }
    }
}

// ---- per-batch stable compaction ----
__global__ void kscan(){
    __shared__ int s[Nn];
    int b = blockIdx.x, tid = threadIdx.x;
    int m = (g_maskf[b*Nn + tid] > 0.0f) ? 1 : 0;
    s[tid] = m;
    __syncthreads();
    for (int off = 1; off < Nn; off <<= 1){
        int t = (tid >= off) ? s[tid-off] : 0;
        __syncthreads();
        s[tid] += t;
        __syncthreads();
    }
    int incl = s[tid];
    int total = s[Nn-1];
    int rank = incl - m;
    int pos = m ? rank : (total + tid - rank);
    g_obsidx[b*Nn + pos] = tid;
    if (tid == 0) g_nobs[b] = total;
}

// ---- tokens[b,i,:] = h_mean[b,obs_idx[i],:] + var_embed[obs_idx[i],:] ----
__global__ void ktokens(const float* __restrict__ var_embed){
    int bn = blockIdx.x;
    int b = bn >> 8, i = bn & 255;
    int tid = threadIdx.x;
    float val = 0.f;
    if (i < g_nobs[b]){
        int src = g_obsidx[b*Nn + i];
        val = g_hmean[(b*Nn + src)*Dd + tid] + var_embed[src*Dd + tid];
    }
    g_tokens[bn*Dd + tid] = val;
}

// ---- q/k/v projections, 16 tokens per block, packed f32x2 ----
__global__ __launch_bounds__(384) void kqkv(
    const float* __restrict__ Wq,
    const float* __restrict__ Wk,
    const float* __restrict__ Wv){
    __shared__ float tokT[Dd][16];     // [d][t]
    int tid = threadIdx.x;
    int b = blockIdx.x >> 4;
    int i0 = (blockIdx.x & 15) * 16;
    for (int idx = tid; idx < 16*Dd; idx += 384){
        int t = idx >> 7, d = idx & 127;
        tokT[d][t] = g_tokens[(b*Nn + i0 + t)*Dd + d];
    }
    __syncthreads();
    int which = tid / Dd, c = tid & 127;
    const float* W = (which == 0) ? Wq : (which == 1 ? Wk : Wv);
    float* dst = (which == 0) ? g_q : (which == 1 ? g_k : g_v);
    unsigned long long acc[8];
    #pragma unroll
    for (int r = 0; r < 8; r++) acc[r] = 0ull;
    for (int d = 0; d < Dd; d++){
        float w = W[d*Dd + c];
        unsigned long long w2; PACKF2(w2, w);
        const ulonglong2* row = (const ulonglong2*)tokT[d];
        #pragma unroll
        for (int r4 = 0; r4 < 4; r4++){
            ulonglong2 p = row[r4];
            FMA2(acc[r4*2+0], p.x, w2, acc[r4*2+0]);
            FMA2(acc[r4*2+1], p.y, w2, acc[r4*2+1]);
        }
    }
    #pragma unroll
    for (int r = 0; r < 8; r++){
        float lo = __uint_as_float((unsigned)(acc[r] & 0xffffffffull));
        float hi = __uint_as_float((unsigned)(acc[r] >> 32));
        dst[(b*Nn + i0 + 2*r    )*Dd + c] = lo;
        dst[(b*Nn + i0 + 2*r + 1)*Dd + c] = hi;
    }
}

// ---- attention per (b,h) ----
__global__ __launch_bounds__(256) void kattn(){
    __shared__ float ks[Nn*17];
    __shared__ float vs[Nn*16];
    __shared__ float qs[8][16];
    __shared__ float pr[8][Nn];
    int b = blockIdx.x / Hh, h = blockIdx.x % Hh;
    int n = g_nobs[b];
    int tid = threadIdx.x;
    for (int idx = tid; idx < n*16; idx += 256){
        int jj = idx >> 4, c = idx & 15;
        ks[jj*17 + c] = g_k[(b*Nn + jj)*Dd + h*16 + c];
        vs[jj*16 + c] = g_v[(b*Nn + jj)*Dd + h*16 + c];
    }
    __syncthreads();
    int w = tid >> 5, lane = tid & 31;
    for (int i = w; i < n; i += 8){
        if (lane < 16) qs[w][lane] = g_q[(b*Nn + i)*Dd + h*16 + lane];
        __syncwarp();
        float sc[8];
        float mx = -1e30f;
        #pragma unroll
        for (int r = 0; r < 8; r++){
            int jj = lane + 32*r;
            float s = -1e30f;
            if (jj < n){
                s = 0.f;
                #pragma unroll
                for (int c = 0; c < 16; c++) s += qs[w][c]*ks[jj*17 + c];
                s *= 0.25f;
            }
            sc[r] = s;
            mx = fmaxf(mx, s);
        }
        #pragma unroll
        for (int off = 16; off; off >>= 1) mx = fmaxf(mx, __shfl_xor_sync(0xffffffffu, mx, off));
        float se = 0.f;
        #pragma unroll
        for (int r = 0; r < 8; r++){
            int jj = lane + 32*r;
            float p = (jj < n) ? expf(sc[r] - mx) : 0.f;
            sc[r] = p; se += p;
        }
        #pragma unroll
        for (int off = 16; off; off >>= 1) se += __shfl_xor_sync(0xffffffffu, se, off);
        float inv = 1.0f/se;
        #pragma unroll
        for (int r = 0; r < 8; r++){
            int jj = lane + 32*r;
            if (jj < n) pr[w][jj] = sc[r]*inv;
        }
        __syncwarp();
        int c = lane & 15, hh = lane >> 4;
        float acc = 0.f;
        for (int jj = hh; jj < n; jj += 2) acc += pr[w][jj]*vs[jj*16 + c];
        acc += __shfl_xor_sync(0xffffffffu, acc, 16);
        if (hh == 0) g_attnv[(b*Nn + i)*Dd + h*16 + c] = acc;
        __syncwarp();
    }
}

// ---- per-batch epilogue ----
__global__ __launch_bounds__(128) void kfinal(
    const float* __restrict__ Wo,
    const float* __restrict__ C,
    const float* __restrict__ Wdec,
    float* __restrict__ outQ,
    float* __restrict__ outW,
    float* __restrict__ outC){
    __shared__ float sa[Dd], Qs[Dd], lg[Kk], wk[Kk], zc[Dd];
    __shared__ float s_alpha, s_conf;
    int b = blockIdx.x, d = threadIdx.x;
    int n = g_nobs[b];
    float a = 0.f, t = 0.f;
    for (int i = 0; i < n; i++){
        a += g_attnv[(b*Nn + i)*Dd + d];
        t += g_tokens[(b*Nn + i)*Dd + d];
    }
    sa[d] = a;
    __syncthreads();
    float q = 0.f;
    #pragma unroll 4
    for (int jj = 0; jj < Dd; jj++) q += sa[jj]*Wo[jj*Dd + d];
    q = (q + t)/(float)n;
    Qs[d] = q;
    __syncthreads();
    if (d < Kk){
        float lgv = 0.f;
        #pragma unroll 4
        for (int dd = 0; dd < Dd; dd++) lgv += Qs[dd]*C[d*Dd + dd];
        lg[d] = lgv * 2.0f;
    }
    __syncthreads();
    if (d == 0){
        float mx = -1e30f;
        for (int k = 0; k < Kk; k++) mx = fmaxf(mx, lg[k]);
        float s = 0.f;
        for (int k = 0; k < Kk; k++){ wk[k] = expf(lg[k]-mx); s += wk[k]; }
        float inv = 1.0f/s, wmax = 0.f;
        for (int k = 0; k < Kk; k++){ wk[k] *= inv; wmax = fmaxf(wmax, wk[k]); }
        float conf = wmax * ((float)n/(float)Nn);
        s_conf = conf;
        s_alpha = 0.1f + 0.9f*conf;
    }
    __syncthreads();
    float z = 0.f;
    #pragma unroll
    for (int k = 0; k < Kk; k++) z += wk[k]*C[k*Dd + d];
    zc[d] = z;
    __syncthreads();
    float f = 0.f;
    #pragma unroll 4
    for (int jj = 0; jj < Dd; jj++) f += zc[jj]*Wdec[jj*Dd + d];
    g_afill[b*Dd + d] = s_alpha * f;
    if (outQ) outQ[b*Dd + d] = q;
    if (outW && d < Kk) outW[b*Kk + d] = wk[d];
    if (outC && d == 0) outC[b] = s_conf;
}

// ---- y_hat, 8 tokens per block, smem-cached transposed W_head ----
__global__ __launch_bounds__(256) void kyhat(
    const float* __restrict__ Wh,
    float* __restrict__ y){
    __shared__ float E[8][Dd];
    __shared__ float sWhT[PLl][Dd];
    int tid = threadIdx.x;
    int bn0 = blockIdx.x*8;
    int b = bn0 >> 8;
    for (int idx = tid; idx < 8*Dd; idx += 256){
        int t = idx >> 7, d = idx & 127;
        float m = g_maskf[bn0+t];
        E[t][d] = g_hmean[(bn0+t)*Dd + d] + (1.0f - m)*g_afill[b*Dd + d];
    }
    for (int idx = tid; idx < Dd*PLl; idx += 256){
        int d = idx / PLl, pl = idx - d*PLl;
        sWhT[pl][d] = Wh[idx];
    }
    __syncthreads();
    if (tid < 192){
        int t = tid / PLl, pl = tid - t*PLl;
        float acc = 0.f;
        const float4* ev = (const float4*)E[t];
        const float4* wv = (const float4*)sWhT[pl];
        #pragma unroll 8
        for (int d4 = 0; d4 < Dd/4; d4++){
            float4 e = ev[d4], w = wv[d4];
            acc += e.x*w.x + e.y*w.y + e.z*w.z + e.w*w.w;
        }
        y[(bn0+t)*PLl + pl] = acc;
    }
}

extern "C" void kernel_launch(void* const* d_in, const int* in_sizes, int n_in,
                              void* d_out, int out_size){
    const float* x    = (const float*)d_in[0];
    const void*  mask = d_in[1];
    const float* Wp   = (const float*)d_in[2];
    const float* bp   = (const float*)d_in[3];
    const float* W1   = (const float*)d_in[4];
    const float* W2   = (const float*)d_in[5];
    const float* ve   = (const float*)d_in[6];
    const float* Wq   = (const float*)d_in[7];
    const float* Wk   = (const float*)d_in[8];
    const float* Wv   = (const float*)d_in[9];
    const float* Wo   = (const float*)d_in[10];
    const float* C    = (const float*)d_in[11];
    const float* Wdec = (const float*)d_in[12];
    const float* Wh   = (const float*)d_in[13];

    float* out = (float*)d_out;
    const int SZ_Y = Bb*Nn*PLl;
    const int SZ_Q = Bb*Dd;
    const int SZ_W = Bb*Kk;
    float* oy = out;
    float* oq = (out_size >= SZ_Y + SZ_Q)              ? out + SZ_Y                : nullptr;
    float* ow = (out_size >= SZ_Y + SZ_Q + SZ_W)       ? out + SZ_Y + SZ_Q         : nullptr;
    float* oc = (out_size >= SZ_Y + SZ_Q + SZ_W + Bb)  ? out + SZ_Y + SZ_Q + SZ_W  : nullptr;

    kdetect<<<1, 256>>>((const unsigned char*)mask);
    kdecode<<<(Bb*Nn + 255)/256, 256>>>(mask);
    kprep<<<1, 256>>>(Wp, bp, W1);
    kstage1<<<Bb*Nn/8, 256>>>(x, Wp, bp, W2);
    kscan<<<Bb, Nn>>>();
    ktokens<<<Bb*Nn, Dd>>>(ve);
    kqkv<<<Bb*Nn/16, 384>>>(Wq, Wk, Wv);
    kattn<<<Bb*Hh, 256>>>();
    kfinal<<<Bb, Dd>>>(Wo, C, Wdec, oq, ow, oc);
    kyhat<<<Bb*Nn/8, 256>>>(Wh, oy);
}

// round 3
// speedup vs baseline: 2.6876x; 1.0915x over previous
#include <cuda_runtime.h>
#include <math.h>

// ---- problem constants ----
#define Bb 64
#define Nn 256
#define Tt 96
#define Pp 8
#define Ss 4
#define Dd 128
#define Hh 8
#define Kk 16
#define PLl 24
#define Ll 23

// ---- scratch ----
__device__ float g_maskf[Bb*Nn];
__device__ int   g_mode;
__device__ float g_wf[9*256];          // rows 0..7: (Wp@W1)[p][j]; row 8: bp@W1
__device__ float g_hmean[Bb*Nn*Dd];
__device__ int   g_obsidx[Bb*Nn];
__device__ int   g_nobs[Bb];
__device__ float g_q[Bb*Nn*Dd];
__device__ float g_k[Bb*Nn*Dd];
__device__ float g_v[Bb*Nn*Dd];
__device__ float g_attnsum[Bb*Dd];     // [b][h*16+c] = sum_i attnv
__device__ float g_toksum[Bb*Dd];
__device__ float g_afill[Bb*Dd];

#define FMA2(d,a,b,c) asm("fma.rn.f32x2 %0, %1, %2, %3;" : "=l"(d) : "l"(a), "l"(b), "l"(c))
#define PACKF2(o,f)   asm("mov.b64 %0, {%1, %1};" : "=l"(o) : "r"(__float_as_uint(f)))
#define PACK2(o,a,b)  asm("mov.b64 %0, {%1, %2};" : "=l"(o) : "r"(__float_as_uint(a)), "r"(__float_as_uint(b)))

__device__ __forceinline__ float f2lo(unsigned long long v){ return __uint_as_float((unsigned)(v & 0xffffffffull)); }
__device__ __forceinline__ float f2hi(unsigned long long v){ return __uint_as_float((unsigned)(v >> 32)); }

__device__ __forceinline__ float gelu_fast(float x){
    // 0.5x(1+tanh(z)), z = 0.79788456*x*(1 + 0.044715 x^2)
    float x2 = x*x;
    float z  = x * fmaf(0.035677408136f, x2, 0.797884560803f);
    float t;
    asm("tanh.approx.f32 %0, %1;" : "=f"(t) : "f"(z));
    float hx = 0.5f*x;
    return fmaf(hx, t, hx);
}

// ---- setup: block 0 = mask dtype sniffer; block 1 = fold Wp/bp into W1 ----
__global__ __launch_bounds__(256) void ksetup(const unsigned char* __restrict__ mp,
                                              const float* __restrict__ Wp,
                                              const float* __restrict__ bp,
                                              const float* __restrict__ W1){
    __shared__ float sWp[Pp*Dd];
    __shared__ float sbp[Dd];
    __shared__ int sawF, sawB;
    int tid = threadIdx.x;
    if (blockIdx.x == 0){
        if (tid == 0){ sawF = 0; sawB = 0; }
        __syncthreads();
        for (int i = tid; i < Bb*Nn; i += 256){
            unsigned char c = mp[i];
            if (c == 0x3f || c == 0x80) sawF = 1;
            else if (c != 0 && (i & 3) != 0) sawB = 1;
        }
        __syncthreads();
        if (tid == 0) g_mode = sawF ? 0 : (sawB ? 2 : 1);
    } else {
        for (int i = tid; i < Pp*Dd; i += 256) sWp[i] = Wp[i];
        if (tid < Dd) sbp[tid] = bp[tid];
        __syncthreads();
        int j = tid;
        float acc[9];
        #pragma unroll
        for (int p = 0; p < 9; p++) acc[p] = 0.f;
        for (int d = 0; d < Dd; d++){
            float w1 = W1[d*256 + j];
            #pragma unroll
            for (int p = 0; p < 8; p++) acc[p] += sWp[p*Dd + d]*w1;
            acc[8] += sbp[d]*w1;
        }
        #pragma unroll
        for (int p = 0; p < 9; p++) g_wf[p*256 + j] = acc[p];
    }
}

// ---- decode mask + stable compaction + zero toksum (one block per batch) ----
__global__ __launch_bounds__(256) void kmask(const void* __restrict__ mp){
    __shared__ int wtot[8];
    __shared__ int wbase[9];
    int b = blockIdx.x, tid = threadIdx.x;
    int i = b*Nn + tid;
    int mode = g_mode;
    bool m;
    if (mode == 0)      m = ((const float*)mp)[i] != 0.0f;
    else if (mode == 1) m = ((const int*)mp)[i]   != 0;
    else                m = ((const unsigned char*)mp)[i] != 0;
    g_maskf[i] = m ? 1.0f : 0.0f;
    unsigned bits = __ballot_sync(0xffffffffu, m);
    int w = tid >> 5, lane = tid & 31;
    int rank = __popc(bits & ((1u << lane) - 1u));
    if (lane == 0) wtot[w] = __popc(bits);
    __syncthreads();
    if (tid == 0){
        int s = 0;
        #pragma unroll
        for (int ww = 0; ww < 8; ww++){ wbase[ww] = s; s += wtot[ww]; }
        wbase[8] = s;
        g_nobs[b] = s;
    }
    __syncthreads();
    int total = wbase[8];
    int obs_before = wbase[w] + rank;
    int pos = m ? obs_before : total + (tid - obs_before);
    g_obsidx[b*Nn + pos] = tid;
    if (tid < Dd) g_toksum[b*Dd + tid] = 0.f;
}

// ---- stage 1: h_mean for 16 tokens per block ----
__global__ __launch_bounds__(256) void kstage1(
    const float* __restrict__ x,
    const float* __restrict__ Wp,
    const float* __restrict__ bp,
    const float* __restrict__ W2){
    __shared__ float sx[16][Tt];                   // masked x
    __shared__ float sxs[16][Pp];                  // per-token column sums
    __shared__ unsigned long long sGp[8][256];     // [tpair][j], packed (t even, t odd)
    __shared__ unsigned long long sv2[8][Dd];      // phase-C partial (upper j half)
    int tid = threadIdx.x;
    int bn0 = blockIdx.x*16;

    for (int idx = tid; idx < 16*Tt; idx += 256){
        int t = idx/Tt, c = idx - t*Tt;
        sx[t][c] = x[(bn0+t)*Tt + c] * g_maskf[bn0+t];
    }
    __syncthreads();
    if (tid < 128){
        int t = tid >> 3, p = tid & 7;
        float s = 0.f;
        #pragma unroll
        for (int l = 0; l < Ll; l++) s += sx[t][l*Ss + p];
        sxs[t][p] = s;
    }

    // phase B: G[t][j] = sum_l gelu(ubias[j] + x_patch_l . Wf[:,j])
    {
        int j = tid;
        float wf[8];
        #pragma unroll
        for (int p = 0; p < 8; p++) wf[p] = g_wf[p*256 + j];
        float ub = g_wf[8*256 + j];
        #pragma unroll 1
        for (int tp = 0; tp < 8; tp++){
            float gg[2];
            #pragma unroll
            for (int s2 = 0; s2 < 2; s2++){
                const float4* xv = (const float4*)sx[tp*2 + s2];
                float4 a = xv[0];
                float g = 0.f;
                #pragma unroll
                for (int l = 0; l < Ll; l++){
                    float4 b2 = xv[l+1];
                    float u = ub + a.x*wf[0] + a.y*wf[1] + a.z*wf[2] + a.w*wf[3]
                                 + b2.x*wf[4] + b2.y*wf[5] + b2.z*wf[6] + b2.w*wf[7];
                    g += gelu_fast(u);
                    a = b2;
                }
                gg[s2] = g;
            }
            unsigned long long pk;
            PACK2(pk, gg[0], gg[1]);
            sGp[tp][j] = pk;
        }
    }
    __syncthreads();

    // phase C: hm[t][d] = (23*bp[d] + xs.Wp[:,d] + sum_j G[t][j] W2[j][d]) / 23
    {
        int d = tid & 127, h2 = tid >> 7;
        unsigned long long acc[8];
        #pragma unroll
        for (int tp = 0; tp < 8; tp++) acc[tp] = 0ull;
        int j0 = h2*128;
        for (int j = j0; j < j0+128; j++){
            float w = W2[j*Dd + d];
            unsigned long long w2; PACKF2(w2, w);
            #pragma unroll
            for (int tp = 0; tp < 8; tp++) FMA2(acc[tp], sGp[tp][j], w2, acc[tp]);
        }
        if (h2){
            #pragma unroll
            for (int tp = 0; tp < 8; tp++) sv2[tp][d] = acc[tp];
        }
        __syncthreads();
        if (!h2){
            float bpd = 23.0f*bp[d];
            float wpc[8];
            #pragma unroll
            for (int p = 0; p < 8; p++) wpc[p] = Wp[p*Dd + d];
            #pragma unroll
            for (int tp = 0; tp < 8; tp++){
                unsigned long long o = sv2[tp][d];
                float lo = f2lo(acc[tp]) + f2lo(o);
                float hi = f2hi(acc[tp]) + f2hi(o);
                int t0 = 2*tp;
                float hs0 = bpd, hs1 = bpd;
                #pragma unroll
                for (int p = 0; p < 8; p++){
                    hs0 += sxs[t0  ][p]*wpc[p];
                    hs1 += sxs[t0+1][p]*wpc[p];
                }
                g_hmean[(bn0+t0  )*Dd + d] = (hs0 + lo) * (1.0f/23.0f);
                g_hmean[(bn0+t0+1)*Dd + d] = (hs1 + hi) * (1.0f/23.0f);
            }
        }
    }
}

// ---- q/k/v projections + token gather + token-sum, 16 tokens per block ----
__global__ __launch_bounds__(384) void kqkv(
    const float* __restrict__ Wq,
    const float* __restrict__ Wk,
    const float* __restrict__ Wv,
    const float* __restrict__ ve){
    __shared__ float tokT[Dd][16];     // [d][t]
    int tid = threadIdx.x;
    int b = blockIdx.x >> 4;
    int i0 = (blockIdx.x & 15) * 16;
    int n = g_nobs[b];
    for (int idx = tid; idx < 16*Dd; idx += 384){
        int t = idx >> 7, d = idx & 127;
        int i = i0 + t;
        float val = 0.f;
        if (i < n){
            int src = g_obsidx[b*Nn + i];
            val = g_hmean[(b*Nn + src)*Dd + d] + ve[src*Dd + d];
        }
        tokT[d][t] = val;
    }
    __syncthreads();
    if (tid < Dd){
        const float4* r = (const float4*)tokT[tid];
        float4 a = r[0], b4 = r[1], c4 = r[2], d4 = r[3];
        float s = a.x+a.y+a.z+a.w + b4.x+b4.y+b4.z+b4.w
                + c4.x+c4.y+c4.z+c4.w + d4.x+d4.y+d4.z+d4.w;
        atomicAdd(&g_toksum[b*Dd + tid], s);
    }
    int which = tid / Dd, c = tid & 127;
    const float* W = (which == 0) ? Wq : (which == 1 ? Wk : Wv);
    float* dst = (which == 0) ? g_q : (which == 1 ? g_k : g_v);
    unsigned long long acc[8];
    #pragma unroll
    for (int r = 0; r < 8; r++) acc[r] = 0ull;
    for (int d = 0; d < Dd; d++){
        float w = W[d*Dd + c];
        unsigned long long w2; PACKF2(w2, w);
        const ulonglong2* row = (const ulonglong2*)tokT[d];
        #pragma unroll
        for (int r4 = 0; r4 < 4; r4++){
            ulonglong2 p = row[r4];
            FMA2(acc[r4*2+0], p.x, w2, acc[r4*2+0]);
            FMA2(acc[r4*2+1], p.y, w2, acc[r4*2+1]);
        }
    }
    #pragma unroll
    for (int r = 0; r < 8; r++){
        dst[(b*Nn + i0 + 2*r    )*Dd + c] = f2lo(acc[r]);
        dst[(b*Nn + i0 + 2*r + 1)*Dd + c] = f2hi(acc[r]);
    }
}

// ---- attention per (b,h); writes only the row-sum of attn@v ----
__global__ __launch_bounds__(256) void kattn(){
    __shared__ float ks[Nn*17];
    __shared__ float vs[Nn*16];
    __shared__ float qs[8][16];
    __shared__ float pr[8][Nn];
    __shared__ float wsum[8][16];
    int b = blockIdx.x / Hh, h = blockIdx.x % Hh;
    int n = g_nobs[b];
    int tid = threadIdx.x;
    for (int idx = tid; idx < n*16; idx += 256){
        int jj = idx >> 4, c = idx & 15;
        ks[jj*17 + c] = g_k[(b*Nn + jj)*Dd + h*16 + c];
        vs[jj*16 + c] = g_v[(b*Nn + jj)*Dd + h*16 + c];
    }
    __syncthreads();
    int w = tid >> 5, lane = tid & 31;
    int c = lane & 15, hh = lane >> 4;
    float osum = 0.f;
    for (int i = w; i < n; i += 8){
        if (lane < 16) qs[w][lane] = g_q[(b*Nn + i)*Dd + h*16 + lane];
        __syncwarp();
        float sc[8];
        float mx = -1e30f;
        #pragma unroll
        for (int r = 0; r < 8; r++){
            int jj = lane + 32*r;
            float s = -1e30f;
            if (jj < n){
                s = 0.f;
                #pragma unroll
                for (int cc = 0; cc < 16; cc++) s += qs[w][cc]*ks[jj*17 + cc];
                s *= 0.25f;
            }
            sc[r] = s;
            mx = fmaxf(mx, s);
        }
        #pragma unroll
        for (int off = 16; off; off >>= 1) mx = fmaxf(mx, __shfl_xor_sync(0xffffffffu, mx, off));
        float se = 0.f;
        #pragma unroll
        for (int r = 0; r < 8; r++){
            int jj = lane + 32*r;
            float p = (jj < n) ? expf(sc[r] - mx) : 0.f;
            sc[r] = p; se += p;
        }
        #pragma unroll
        for (int off = 16; off; off >>= 1) se += __shfl_xor_sync(0xffffffffu, se, off);
        float inv = 1.0f/se;
        #pragma unroll
        for (int r = 0; r < 8; r++){
            int jj = lane + 32*r;
            if (jj < n) pr[w][jj] = sc[r]*inv;
        }
        __syncwarp();
        float acc = 0.f;
        for (int jj = hh; jj < n; jj += 2) acc += pr[w][jj]*vs[jj*16 + c];
        acc += __shfl_xor_sync(0xffffffffu, acc, 16);
        if (hh == 0) osum += acc;
        __syncwarp();
    }
    if (hh == 0) wsum[w][c] = osum;
    __syncthreads();
    if (tid < 16){
        float s = 0.f;
        #pragma unroll
        for (int ww = 0; ww < 8; ww++) s += wsum[ww][tid];
        g_attnsum[b*Dd + h*16 + tid] = s;
    }
}

// ---- per-batch epilogue (no serial n-loops) ----
__global__ __launch_bounds__(128) void kfinal(
    const float* __restrict__ Wo,
    const float* __restrict__ C,
    const float* __restrict__ Wdec,
    float* __restrict__ outQ,
    float* __restrict__ outW,
    float* __restrict__ outC){
    __shared__ float sa[Dd], Qs[Dd], lg[Kk], wk[Kk], zc[Dd];
    __shared__ float s_alpha, s_conf;
    int b = blockIdx.x, d = threadIdx.x;
    int n = g_nobs[b];
    sa[d] = g_attnsum[b*Dd + d];
    __syncthreads();
    float q = 0.f;
    #pragma unroll 4
    for (int jj = 0; jj < Dd; jj++) q += sa[jj]*Wo[jj*Dd + d];
    q = (q + g_toksum[b*Dd + d])/(float)n;
    Qs[d] = q;
    __syncthreads();
    if (d < Kk){
        float lgv = 0.f;
        #pragma unroll 4
        for (int dd = 0; dd < Dd; dd++) lgv += Qs[dd]*C[d*Dd + dd];
        lg[d] = lgv * 2.0f;
    }
    __syncthreads();
    if (d == 0){
        float mx = -1e30f;
        for (int k = 0; k < Kk; k++) mx = fmaxf(mx, lg[k]);
        float s = 0.f;
        for (int k = 0; k < Kk; k++){ wk[k] = expf(lg[k]-mx); s += wk[k]; }
        float inv = 1.0f/s, wmax = 0.f;
        for (int k = 0; k < Kk; k++){ wk[k] *= inv; wmax = fmaxf(wmax, wk[k]); }
        float conf = wmax * ((float)n/(float)Nn);
        s_conf = conf;
        s_alpha = 0.1f + 0.9f*conf;
    }
    __syncthreads();
    float z = 0.f;
    #pragma unroll
    for (int k = 0; k < Kk; k++) z += wk[k]*C[k*Dd + d];
    zc[d] = z;
    __syncthreads();
    float f = 0.f;
    #pragma unroll 4
    for (int jj = 0; jj < Dd; jj++) f += zc[jj]*Wdec[jj*Dd + d];
    g_afill[b*Dd + d] = s_alpha * f;
    if (outQ) outQ[b*Dd + d] = q;
    if (outW && d < Kk) outW[b*Kk + d] = wk[d];
    if (outC && d == 0) outC[b] = s_conf;
}

// ---- y_hat, 8 tokens per block ----
__global__ __launch_bounds__(256) void kyhat(
    const float* __restrict__ Wh,
    float* __restrict__ y){
    __shared__ float E[8][Dd];
    __shared__ float sWhT[PLl][Dd];
    int tid = threadIdx.x;
    int bn0 = blockIdx.x*8;
    int b = bn0 >> 8;
    for (int idx = tid; idx < 8*Dd; idx += 256){
        int t = idx >> 7, d = idx & 127;
        float m = g_maskf[bn0+t];
        E[t][d] = g_hmean[(bn0+t)*Dd + d] + (1.0f - m)*g_afill[b*Dd + d];
    }
    for (int idx = tid; idx < Dd*PLl; idx += 256){
        int d = idx / PLl, pl = idx - d*PLl;
        sWhT[pl][d] = Wh[idx];
    }
    __syncthreads();
    if (tid < 192){
        int t = tid / PLl, pl = tid - t*PLl;
        float acc = 0.f;
        const float4* ev = (const float4*)E[t];
        const float4* wv = (const float4*)sWhT[pl];
        #pragma unroll 8
        for (int d4 = 0; d4 < Dd/4; d4++){
            float4 e = ev[d4], w = wv[d4];
            acc += e.x*w.x + e.y*w.y + e.z*w.z + e.w*w.w;
        }
        y[(bn0+t)*PLl + pl] = acc;
    }
}

extern "C" void kernel_launch(void* const* d_in, const int* in_sizes, int n_in,
                              void* d_out, int out_size){
    const float* x    = (const float*)d_in[0];
    const void*  mask = d_in[1];
    const float* Wp   = (const float*)d_in[2];
    const float* bp   = (const float*)d_in[3];
    const float* W1   = (const float*)d_in[4];
    const float* W2   = (const float*)d_in[5];
    const float* ve   = (const float*)d_in[6];
    const float* Wq   = (const float*)d_in[7];
    const float* Wk   = (const float*)d_in[8];
    const float* Wv   = (const float*)d_in[9];
    const float* Wo   = (const float*)d_in[10];
    const float* C    = (const float*)d_in[11];
    const float* Wdec = (const float*)d_in[12];
    const float* Wh   = (const float*)d_in[13];

    float* out = (float*)d_out;
    const int SZ_Y = Bb*Nn*PLl;
    const int SZ_Q = Bb*Dd;
    const int SZ_W = Bb*Kk;
    float* oy = out;
    float* oq = (out_size >= SZ_Y + SZ_Q)              ? out + SZ_Y                : nullptr;
    float* ow = (out_size >= SZ_Y + SZ_Q + SZ_W)       ? out + SZ_Y + SZ_Q         : nullptr;
    float* oc = (out_size >= SZ_Y + SZ_Q + SZ_W + Bb)  ? out + SZ_Y + SZ_Q + SZ_W  : nullptr;

    ksetup<<<2, 256>>>((const unsigned char*)mask, Wp, bp, W1);
    kmask<<<Bb, 256>>>(mask);
    kstage1<<<Bb*Nn/16, 256>>>(x, Wp, bp, W2);
    kqkv<<<Bb*Nn/16, 384>>>(Wq, Wk, Wv, ve);
    kattn<<<Bb*Hh, 256>>>();
    kfinal<<<Bb, Dd>>>(Wo, C, Wdec, oq, ow, oc);
    kyhat<<<Bb*Nn/8, 256>>>(Wh, oy);
}

// round 7
// speedup vs baseline: 2.9234x; 1.0878x over previous
#include <cuda_runtime.h>
#include <math.h>

// ---- problem constants ----
#define Bb 64
#define Nn 256
#define Tt 96
#define Pp 8
#define Ss 4
#define Dd 128
#define Hh 8
#define Kk 16
#define PLl 24
#define Ll 23

// ---- scratch ----
__device__ float g_maskf[Bb*Nn];
__device__ float g_wf[9*256];          // rows 0..7: (Wp@W1)[p][j]; row 8: bp@W1
__device__ __align__(16) float g_hmean[Bb*Nn*Dd];
__device__ int   g_obsidx[Bb*Nn];
__device__ int   g_nobs[Bb];
__device__ __align__(16) float g_q[Bb*Nn*Dd];
__device__ __align__(16) float g_k[Bb*Nn*Dd];
__device__ __align__(16) float g_v[Bb*Nn*Dd];
__device__ float g_attnsum[Bb*Dd];
__device__ float g_toksum[Bb*Dd];

typedef unsigned long long u64;

#define FMA2(d,a,b,c) asm("fma.rn.f32x2 %0, %1, %2, %3;" : "=l"(d) : "l"(a), "l"(b), "l"(c))
#define MUL2(d,a,b)   asm("mul.rn.f32x2 %0, %1, %2;" : "=l"(d) : "l"(a), "l"(b))
#define ADD2(d,a,b)   asm("add.rn.f32x2 %0, %1, %2;" : "=l"(d) : "l"(a), "l"(b))
#define PACKF2(o,f)   asm("mov.b64 %0, {%1, %1};" : "=l"(o) : "r"(__float_as_uint(f)))
#define PACK2(o,a,b)  asm("mov.b64 %0, {%1, %2};" : "=l"(o) : "r"(__float_as_uint(a)), "r"(__float_as_uint(b)))
#define UNPACK2(a,b,i) asm("mov.b64 {%0, %1}, %2;" : "=r"(a), "=r"(b) : "l"(i))

__device__ __forceinline__ float f2lo(u64 v){ return __uint_as_float((unsigned)(v & 0xffffffffull)); }
__device__ __forceinline__ float f2hi(u64 v){ return __uint_as_float((unsigned)(v >> 32)); }

__device__ __forceinline__ float tanh_fast(float z){
    float t;
    asm("tanh.approx.f32 %0, %1;" : "=f"(t) : "f"(z));
    return t;
}

// ---- fused: blocks 0..63 = mask decode + compaction (per-block dtype sniff);
//             block 64 = fold Wp/bp into W1 ----
__global__ __launch_bounds__(256) void kmaskfold(const unsigned char* __restrict__ mp,
                                                 const float* __restrict__ Wp,
                                                 const float* __restrict__ bp,
                                                 const float* __restrict__ W1){
    int tid = threadIdx.x;
    if (blockIdx.x == Bb){
        __shared__ float sWp[Pp*Dd];
        __shared__ float sbp[Dd];
        for (int i = tid; i < Pp*Dd; i += 256) sWp[i] = Wp[i];
        if (tid < Dd) sbp[tid] = bp[tid];
        __syncthreads();
        int j = tid;
        float acc[9];
        #pragma unroll
        for (int p = 0; p < 9; p++) acc[p] = 0.f;
        for (int d = 0; d < Dd; d++){
            float w1 = W1[d*256 + j];
            #pragma unroll
            for (int p = 0; p < 8; p++) acc[p] += sWp[p*Dd + d]*w1;
            acc[8] += sbp[d]*w1;
        }
        #pragma unroll
        for (int p = 0; p < 9; p++) g_wf[p*256 + j] = acc[p];
        return;
    }
    // mask blocks: local dtype sniff over the first B*N bytes
    __shared__ int sawF, sawB;
    __shared__ int wtot[8];
    __shared__ int wbase[9];
    if (tid == 0){ sawF = 0; sawB = 0; }
    __syncthreads();
    for (int i = tid; i < Bb*Nn; i += 256){
        unsigned char c = mp[i];
        if (c == 0x3f || c == 0x80) sawF = 1;
        else if (c != 0 && (i & 3) != 0) sawB = 1;
    }
    __syncthreads();
    int mode = sawF ? 0 : (sawB ? 2 : 1);
    int b = blockIdx.x;
    int i = b*Nn + tid;
    bool m;
    if (mode == 0)      m = ((const float*)mp)[i] != 0.0f;
    else if (mode == 1) m = ((const int*)mp)[i]   != 0;
    else                m = mp[i] != 0;
    g_maskf[i] = m ? 1.0f : 0.0f;
    unsigned bits = __ballot_sync(0xffffffffu, m);
    int w = tid >> 5, lane = tid & 31;
    int rank = __popc(bits & ((1u << lane) - 1u));
    if (lane == 0) wtot[w] = __popc(bits);
    __syncthreads();
    if (tid == 0){
        int s = 0;
        #pragma unroll
        for (int ww = 0; ww < 8; ww++){ wbase[ww] = s; s += wtot[ww]; }
        wbase[8] = s;
        g_nobs[b] = s;
    }
    __syncthreads();
    int total = wbase[8];
    int obs_before = wbase[w] + rank;
    int pos = m ? obs_before : total + (tid - obs_before);
    g_obsidx[b*Nn + pos] = tid;
    if (tid < Dd) g_toksum[b*Dd + tid] = 0.f;
}

// ---- stage 1: h_mean for 16 tokens per block, fully packed f32x2 ----
__global__ __launch_bounds__(256) void kstage1(
    const float* __restrict__ x,
    const float* __restrict__ Wp,
    const float* __restrict__ bp,
    const float* __restrict__ W2){
    __shared__ __align__(16) u64 sxp[8][96];    // [tpair][col] packed (even tok lo, odd tok hi)
    __shared__ float sxs[16][Pp];               // per-token patch-column sums
    __shared__ __align__(16) u64 sG2[256][10];  // [j][tpair], pad 10, 16B-aligned rows
    __shared__ u64 sv2[8][Dd];                  // phase-C partial (upper j half)
    int tid = threadIdx.x;
    int bn0 = blockIdx.x*16;

    for (int idx = tid; idx < 8*Tt; idx += 256){
        int tp = idx/Tt, c = idx - tp*Tt;
        float lo = x[(bn0+2*tp  )*Tt + c] * g_maskf[bn0+2*tp];
        float hi = x[(bn0+2*tp+1)*Tt + c] * g_maskf[bn0+2*tp+1];
        u64 pk; PACK2(pk, lo, hi);
        sxp[tp][c] = pk;
    }
    __syncthreads();
    if (tid < 128){
        int t = tid >> 3, p = tid & 7;
        int tp = t >> 1, half = t & 1;
        float s = 0.f;
        #pragma unroll
        for (int l = 0; l < Ll; l++){
            u64 v = sxp[tp][l*Ss + p];
            s += half ? f2hi(v) : f2lo(v);
        }
        sxs[t][p] = s;
    }

    // phase B: packed u + packed gelu
    {
        int j = tid;
        u64 wf2[8];
        #pragma unroll
        for (int p = 0; p < 8; p++) PACKF2(wf2[p], g_wf[p*256 + j]);
        u64 ub2; PACKF2(ub2, g_wf[8*256 + j]);
        u64 C1P, C2P, HALFP;
        PACKF2(C1P, 0.035677408136f);
        PACKF2(C2P, 0.797884560803f);
        PACKF2(HALFP, 0.5f);
        #pragma unroll 1
        for (int tp = 0; tp < 8; tp++){
            const ulonglong2* xv = (const ulonglong2*)&sxp[tp][0];
            ulonglong2 A = xv[0], Bv = xv[1];
            u64 Gp = 0ull;
            #pragma unroll
            for (int l = 0; l < Ll; l++){
                ulonglong2 Cv = xv[2*l+2], Dv = xv[2*l+3];
                u64 u = ub2;
                FMA2(u, A.x,  wf2[0], u); FMA2(u, A.y,  wf2[1], u);
                FMA2(u, Bv.x, wf2[2], u); FMA2(u, Bv.y, wf2[3], u);
                FMA2(u, Cv.x, wf2[4], u); FMA2(u, Cv.y, wf2[5], u);
                FMA2(u, Dv.x, wf2[6], u); FMA2(u, Dv.y, wf2[7], u);
                // packed gelu: 0.5x(1+tanh(x*(c2 + c1 x^2)))
                u64 x2p; MUL2(x2p, u, u);
                u64 t1;  FMA2(t1, C1P, x2p, C2P);
                u64 zp;  MUL2(zp, u, t1);
                unsigned zl, zh; UNPACK2(zl, zh, zp);
                float tl = tanh_fast(__uint_as_float(zl));
                float th = tanh_fast(__uint_as_float(zh));
                u64 tpk; PACK2(tpk, tl, th);
                u64 hxp; MUL2(hxp, u, HALFP);
                u64 res; FMA2(res, hxp, tpk, hxp);
                ADD2(Gp, Gp, res);
                A = Cv; Bv = Dv;
            }
            sG2[j][tp] = Gp;
        }
    }
    __syncthreads();

    // phase C: hm[t][d] = (23*bp[d] + xs.Wp[:,d] + sum_j G[t][j] W2[j][d]) / 23
    {
        int d = tid & 127, h2 = tid >> 7;
        u64 acc[8];
        #pragma unroll
        for (int tp = 0; tp < 8; tp++) acc[tp] = 0ull;
        int j0 = h2*128;
        for (int j = j0; j < j0+128; j++){
            float w = W2[j*Dd + d];
            u64 w2; PACKF2(w2, w);
            const ulonglong2* gr = (const ulonglong2*)&sG2[j][0];
            ulonglong2 g01 = gr[0], g23 = gr[1], g45 = gr[2], g67 = gr[3];
            FMA2(acc[0], g01.x, w2, acc[0]); FMA2(acc[1], g01.y, w2, acc[1]);
            FMA2(acc[2], g23.x, w2, acc[2]); FMA2(acc[3], g23.y, w2, acc[3]);
            FMA2(acc[4], g45.x, w2, acc[4]); FMA2(acc[5], g45.y, w2, acc[5]);
            FMA2(acc[6], g67.x, w2, acc[6]); FMA2(acc[7], g67.y, w2, acc[7]);
        }
        if (h2){
            #pragma unroll
            for (int tp = 0; tp < 8; tp++) sv2[tp][d] = acc[tp];
        }
        __syncthreads();
        if (!h2){
            float bpd = 23.0f*bp[d];
            float wpc[8];
            #pragma unroll
            for (int p = 0; p < 8; p++) wpc[p] = Wp[p*Dd + d];
            #pragma unroll
            for (int tp = 0; tp < 8; tp++){
                u64 o = sv2[tp][d];
                float lo = f2lo(acc[tp]) + f2lo(o);
                float hi = f2hi(acc[tp]) + f2hi(o);
                int t0 = 2*tp;
                float hs0 = bpd, hs1 = bpd;
                #pragma unroll
                for (int p = 0; p < 8; p++){
                    hs0 += sxs[t0  ][p]*wpc[p];
                    hs1 += sxs[t0+1][p]*wpc[p];
                }
                g_hmean[(bn0+t0  )*Dd + d] = (hs0 + lo) * (1.0f/23.0f);
                g_hmean[(bn0+t0+1)*Dd + d] = (hs1 + hi) * (1.0f/23.0f);
            }
        }
    }
}

// ---- q/k/v: 16 tokens/block, 192 threads = 3 proj x 64 column-pairs ----
__global__ __launch_bounds__(192, 4) void kqkv(
    const float* __restrict__ Wq,
    const float* __restrict__ Wk,
    const float* __restrict__ Wv,
    const float* __restrict__ ve){
    __shared__ __align__(16) float tokT[Dd][20];   // [d][t], pad 20, 16B-aligned rows
    int tid = threadIdx.x;
    int b = blockIdx.x >> 4;
    int i0 = (blockIdx.x & 15) * 16;
    int n = g_nobs[b];
    for (int idx = tid; idx < 16*Dd; idx += 192){
        int t = idx >> 7, d = idx & 127;
        int i = i0 + t;
        float val = 0.f;
        if (i < n){
            int src = g_obsidx[b*Nn + i];
            val = g_hmean[(b*Nn + src)*Dd + d] + ve[src*Dd + d];
        }
        tokT[d][t] = val;
    }
    __syncthreads();
    if (tid < Dd){
        const float4* r = (const float4*)&tokT[tid][0];
        float4 a = r[0], b4 = r[1], c4 = r[2], d4 = r[3];
        float s = a.x+a.y+a.z+a.w + b4.x+b4.y+b4.z+b4.w
                + c4.x+c4.y+c4.z+c4.w + d4.x+d4.y+d4.z+d4.w;
        atomicAdd(&g_toksum[b*Dd + tid], s);
    }
    int which = tid >> 6;               // 0=q,1=k,2=v
    int c0 = (tid & 63) * 2;
    const float* W = (which == 0) ? Wq : (which == 1 ? Wk : Wv);
    float* dst = (which == 0) ? g_q : (which == 1 ? g_k : g_v);
    u64 a0[8], a1[8];
    #pragma unroll
    for (int r = 0; r < 8; r++){ a0[r] = 0ull; a1[r] = 0ull; }
    for (int d = 0; d < Dd; d++){
        float2 w = *(const float2*)&W[d*Dd + c0];
        u64 w2a, w2b;
        PACKF2(w2a, w.x);
        PACKF2(w2b, w.y);
        const ulonglong2* row = (const ulonglong2*)&tokT[d][0];
        ulonglong2 p0 = row[0], p1 = row[1], p2 = row[2], p3 = row[3];
        FMA2(a0[0], p0.x, w2a, a0[0]); FMA2(a1[0], p0.x, w2b, a1[0]);
        FMA2(a0[1], p0.y, w2a, a0[1]); FMA2(a1[1], p0.y, w2b, a1[1]);
        FMA2(a0[2], p1.x, w2a, a0[2]); FMA2(a1[2], p1.x, w2b, a1[2]);
        FMA2(a0[3], p1.y, w2a, a0[3]); FMA2(a1[3], p1.y, w2b, a1[3]);
        FMA2(a0[4], p2.x, w2a, a0[4]); FMA2(a1[4], p2.x, w2b, a1[4]);
        FMA2(a0[5], p2.y, w2a, a0[5]); FMA2(a1[5], p2.y, w2b, a1[5]);
        FMA2(a0[6], p3.x, w2a, a0[6]); FMA2(a1[6], p3.x, w2b, a1[6]);
        FMA2(a0[7], p3.y, w2a, a0[7]); FMA2(a1[7], p3.y, w2b, a1[7]);
    }
    #pragma unroll
    for (int r = 0; r < 8; r++){
        float2 e0 = make_float2(f2lo(a0[r]), f2lo(a1[r]));   // token 2r
        float2 e1 = make_float2(f2hi(a0[r]), f2hi(a1[r]));   // token 2r+1
        *(float2*)&dst[(b*Nn + i0 + 2*r    )*Dd + c0] = e0;
        *(float2*)&dst[(b*Nn + i0 + 2*r + 1)*Dd + c0] = e1;
    }
}

// ---- attention per (b,h); writes only the row-sum of attn@v ----
__global__ __launch_bounds__(256) void kattn(){
    __shared__ float ks[Nn*17];
    __shared__ float vs[Nn*16];
    __shared__ float qs[8][16];
    __shared__ float pr[8][Nn];
    __shared__ float wsum[8][16];
    int b = blockIdx.x / Hh, h = blockIdx.x % Hh;
    int n = g_nobs[b];
    int tid = threadIdx.x;
    for (int idx = tid; idx < n*16; idx += 256){
        int jj = idx >> 4, c = idx & 15;
        ks[jj*17 + c] = g_k[(b*Nn + jj)*Dd + h*16 + c];
        vs[jj*16 + c] = g_v[(b*Nn + jj)*Dd + h*16 + c];
    }
    __syncthreads();
    int w = tid >> 5, lane = tid & 31;
    int c = lane & 15, hh = lane >> 4;
    float osum = 0.f;
    for (int i = w; i < n; i += 8){
        if (lane < 16) qs[w][lane] = g_q[(b*Nn + i)*Dd + h*16 + lane];
        __syncwarp();
        float sc[8];
        float mx = -1e30f;
        #pragma unroll
        for (int r = 0; r < 8; r++){
            int jj = lane + 32*r;
            float s = -1e30f;
            if (jj < n){
                s = 0.f;
                #pragma unroll
                for (int cc = 0; cc < 16; cc++) s += qs[w][cc]*ks[jj*17 + cc];
                s *= 0.25f;
            }
            sc[r] = s;
            mx = fmaxf(mx, s);
        }
        #pragma unroll
        for (int off = 16; off; off >>= 1) mx = fmaxf(mx, __shfl_xor_sync(0xffffffffu, mx, off));
        float se = 0.f;
        #pragma unroll
        for (int r = 0; r < 8; r++){
            int jj = lane + 32*r;
            float p = (jj < n) ? expf(sc[r] - mx) : 0.f;
            sc[r] = p; se += p;
        }
        #pragma unroll
        for (int off = 16; off; off >>= 1) se += __shfl_xor_sync(0xffffffffu, se, off);
        float inv = 1.0f/se;
        #pragma unroll
        for (int r = 0; r < 8; r++){
            int jj = lane + 32*r;
            if (jj < n) pr[w][jj] = sc[r]*inv;
        }
        __syncwarp();
        float acc = 0.f;
        for (int jj = hh; jj < n; jj += 2) acc += pr[w][jj]*vs[jj*16 + c];
        acc += __shfl_xor_sync(0xffffffffu, acc, 16);
        if (hh == 0) osum += acc;
        __syncwarp();
    }
    if (hh == 0) wsum[w][c] = osum;
    __syncthreads();
    if (tid < 16){
        float s = 0.f;
        #pragma unroll
        for (int ww = 0; ww < 8; ww++) s += wsum[ww][tid];
        g_attnsum[b*Dd + h*16 + tid] = s;
    }
}

// ---- per-batch: epilogue (Q_sub/w_sub/conf/fill) + y_hat for all 256 tokens ----
__global__ __launch_bounds__(256) void kfinaly(
    const float* __restrict__ Wo,
    const float* __restrict__ C,
    const float* __restrict__ Wdec,
    const float* __restrict__ Wh,
    float* __restrict__ y,
    float* __restrict__ outQ,
    float* __restrict__ outW,
    float* __restrict__ outC){
    __shared__ float sa[Dd], Qs[Dd], lg[Kk], wk[Kk], zc[Dd], saf[Dd];
    __shared__ float s_alpha, s_conf;
    __shared__ __align__(16) float sWhT[PLl][132];
    __shared__ __align__(16) float E[8][Dd];
    int b = blockIdx.x, tid = threadIdx.x;
    int n = g_nobs[b];
    // load transposed head weights
    for (int idx = tid; idx < Dd*PLl; idx += 256){
        int d = idx / PLl, pl = idx - d*PLl;
        sWhT[pl][d] = Wh[idx];
    }
    if (tid < Dd) sa[tid] = g_attnsum[b*Dd + tid];
    __syncthreads();
    if (tid < Dd){
        float q = 0.f;
        #pragma unroll 4
        for (int jj = 0; jj < Dd; jj++) q += sa[jj]*Wo[jj*Dd + tid];
        q = (q + g_toksum[b*Dd + tid])/(float)n;
        Qs[tid] = q;
        if (outQ) outQ[b*Dd + tid] = q;
    }
    __syncthreads();
    if (tid < Kk){
        float lgv = 0.f;
        #pragma unroll 4
        for (int dd = 0; dd < Dd; dd++) lgv += Qs[dd]*C[tid*Dd + dd];
        lg[tid] = lgv * 2.0f;
    }
    __syncthreads();
    if (tid == 0){
        float mx = -1e30f;
        for (int k = 0; k < Kk; k++) mx = fmaxf(mx, lg[k]);
        float s = 0.f;
        for (int k = 0; k < Kk; k++){ wk[k] = expf(lg[k]-mx); s += wk[k]; }
        float inv = 1.0f/s, wmax = 0.f;
        for (int k = 0; k < Kk; k++){ wk[k] *= inv; wmax = fmaxf(wmax, wk[k]); }
        float conf = wmax * ((float)n/(float)Nn);
        s_conf = conf;
        s_alpha = 0.1f + 0.9f*conf;
        if (outC) outC[b] = conf;
    }
    __syncthreads();
    if (tid < Dd){
        float z = 0.f;
        #pragma unroll
        for (int k = 0; k < Kk; k++) z += wk[k]*C[k*Dd + tid];
        zc[tid] = z;
        if (outW && tid < Kk) outW[b*Kk + tid] = wk[tid];
    }
    __syncthreads();
    if (tid < Dd){
        float f = 0.f;
        #pragma unroll 4
        for (int jj = 0; jj < Dd; jj++) f += zc[jj]*Wdec[jj*Dd + tid];
        saf[tid] = s_alpha * f;
    }
    __syncthreads();
    // y_hat for this batch's 256 tokens, 8-token tiles
    for (int tt = 0; tt < 32; tt++){
        int bn0 = b*Nn + tt*8;
        for (int idx = tid; idx < 8*Dd; idx += 256){
            int t = idx >> 7, d = idx & 127;
            float m = g_maskf[bn0+t];
            E[t][d] = g_hmean[(bn0+t)*Dd + d] + (1.0f - m)*saf[d];
        }
        __syncthreads();
        if (tid < 192){
            int t = tid / PLl, pl = tid - t*PLl;
            float acc = 0.f;
            const float4* ev = (const float4*)&E[t][0];
            const float4* wv = (const float4*)&sWhT[pl][0];
            #pragma unroll 8
            for (int d4 = 0; d4 < Dd/4; d4++){
                float4 e = ev[d4], w = wv[d4];
                acc += e.x*w.x + e.y*w.y + e.z*w.z + e.w*w.w;
            }
            y[(bn0+t)*PLl + pl] = acc;
        }
        __syncthreads();
    }
}

extern "C" void kernel_launch(void* const* d_in, const int* in_sizes, int n_in,
                              void* d_out, int out_size){
    const float* x    = (const float*)d_in[0];
    const void*  mask = d_in[1];
    const float* Wp   = (const float*)d_in[2];
    const float* bp   = (const float*)d_in[3];
    const float* W1   = (const float*)d_in[4];
    const float* W2   = (const float*)d_in[5];
    const float* ve   = (const float*)d_in[6];
    const float* Wq   = (const float*)d_in[7];
    const float* Wk   = (const float*)d_in[8];
    const float* Wv   = (const float*)d_in[9];
    const float* Wo   = (const float*)d_in[10];
    const float* C    = (const float*)d_in[11];
    const float* Wdec = (const float*)d_in[12];
    const float* Wh   = (const float*)d_in[13];

    float* out = (float*)d_out;
    const int SZ_Y = Bb*Nn*PLl;
    const int SZ_Q = Bb*Dd;
    const int SZ_W = Bb*Kk;
    float* oy = out;
    float* oq = (out_size >= SZ_Y + SZ_Q)              ? out + SZ_Y                : nullptr;
    float* ow = (out_size >= SZ_Y + SZ_Q + SZ_W)       ? out + SZ_Y + SZ_Q         : nullptr;
    float* oc = (out_size >= SZ_Y + SZ_Q + SZ_W + Bb)  ? out + SZ_Y + SZ_Q + SZ_W  : nullptr;

    kmaskfold<<<Bb+1, 256>>>((const unsigned char*)mask, Wp, bp, W1);
    kstage1<<<Bb*Nn/16, 256>>>(x, Wp, bp, W2);
    kqkv<<<Bb*Nn/16, 192>>>(Wq, Wk, Wv, ve);
    kattn<<<Bb*Hh, 256>>>();
    kfinaly<<<Bb, 256>>>(Wo, C, Wdec, Wh, oy, oq, ow, oc);
}

// round 8
// speedup vs baseline: 3.9122x; 1.3382x over previous
#include <cuda_runtime.h>
#include <math.h>

// ---- problem constants ----
#define Bb 64
#define Nn 256
#define Tt 96
#define Pp 8
#define Ss 4
#define Dd 128
#define Hh 8
#define Kk 16
#define PLl 24
#define Ll 23

// ---- scratch ----
__device__ float g_maskf[Bb*Nn];
__device__ float g_wf[9*256];          // rows 0..7: (Wp@W1)[p][j]; row 8: bp@W1
__device__ __align__(16) float g_hmean[Bb*Nn*Dd];
__device__ int   g_obsidx[Bb*Nn];
__device__ int   g_nobs[Bb];
__device__ __align__(16) float g_q[Bb*Nn*Dd];
__device__ __align__(16) float g_k[Bb*Nn*Dd];
__device__ __align__(16) float g_v[Bb*Nn*Dd];
__device__ float g_attnsum[Bb*Dd];
__device__ float g_toksum[Bb*Dd];

typedef unsigned long long u64;

#define FMA2(d,a,b,c) asm("fma.rn.f32x2 %0, %1, %2, %3;" : "=l"(d) : "l"(a), "l"(b), "l"(c))
#define MUL2(d,a,b)   asm("mul.rn.f32x2 %0, %1, %2;" : "=l"(d) : "l"(a), "l"(b))
#define ADD2(d,a,b)   asm("add.rn.f32x2 %0, %1, %2;" : "=l"(d) : "l"(a), "l"(b))
#define PACKF2(o,f)   asm("mov.b64 %0, {%1, %1};" : "=l"(o) : "r"(__float_as_uint(f)))
#define PACK2(o,a,b)  asm("mov.b64 %0, {%1, %2};" : "=l"(o) : "r"(__float_as_uint(a)), "r"(__float_as_uint(b)))
#define UNPACK2(a,b,i) asm("mov.b64 {%0, %1}, %2;" : "=r"(a), "=r"(b) : "l"(i))

__device__ __forceinline__ float f2lo(u64 v){ return __uint_as_float((unsigned)(v & 0xffffffffull)); }
__device__ __forceinline__ float f2hi(u64 v){ return __uint_as_float((unsigned)(v >> 32)); }

__device__ __forceinline__ float tanh_fast(float z){
    float t;
    asm("tanh.approx.f32 %0, %1;" : "=f"(t) : "f"(z));
    return t;
}

// ---- fused: blocks 0..63 = mask decode + compaction (per-block dtype sniff);
//             block 64 = fold Wp/bp into W1 ----
__global__ __launch_bounds__(256) void kmaskfold(const unsigned char* __restrict__ mp,
                                                 const float* __restrict__ Wp,
                                                 const float* __restrict__ bp,
                                                 const float* __restrict__ W1){
    int tid = threadIdx.x;
    if (blockIdx.x == Bb){
        __shared__ float sWp[Pp*Dd];
        __shared__ float sbp[Dd];
        for (int i = tid; i < Pp*Dd; i += 256) sWp[i] = Wp[i];
        if (tid < Dd) sbp[tid] = bp[tid];
        __syncthreads();
        int j = tid;
        float acc[9];
        #pragma unroll
        for (int p = 0; p < 9; p++) acc[p] = 0.f;
        for (int d = 0; d < Dd; d++){
            float w1 = W1[d*256 + j];
            #pragma unroll
            for (int p = 0; p < 8; p++) acc[p] += sWp[p*Dd + d]*w1;
            acc[8] += sbp[d]*w1;
        }
        #pragma unroll
        for (int p = 0; p < 9; p++) g_wf[p*256 + j] = acc[p];
        return;
    }
    // mask blocks: local dtype sniff over the first B*N bytes
    __shared__ int sawF, sawB;
    __shared__ int wtot[8];
    __shared__ int wbase[9];
    if (tid == 0){ sawF = 0; sawB = 0; }
    __syncthreads();
    for (int i = tid; i < Bb*Nn; i += 256){
        unsigned char c = mp[i];
        if (c == 0x3f || c == 0x80) sawF = 1;
        else if (c != 0 && (i & 3) != 0) sawB = 1;
    }
    __syncthreads();
    int mode = sawF ? 0 : (sawB ? 2 : 1);
    int b = blockIdx.x;
    int i = b*Nn + tid;
    bool m;
    if (mode == 0)      m = ((const float*)mp)[i] != 0.0f;
    else if (mode == 1) m = ((const int*)mp)[i]   != 0;
    else                m = mp[i] != 0;
    g_maskf[i] = m ? 1.0f : 0.0f;
    unsigned bits = __ballot_sync(0xffffffffu, m);
    int w = tid >> 5, lane = tid & 31;
    int rank = __popc(bits & ((1u << lane) - 1u));
    if (lane == 0) wtot[w] = __popc(bits);
    __syncthreads();
    if (tid == 0){
        int s = 0;
        #pragma unroll
        for (int ww = 0; ww < 8; ww++){ wbase[ww] = s; s += wtot[ww]; }
        wbase[8] = s;
        g_nobs[b] = s;
    }
    __syncthreads();
    int total = wbase[8];
    int obs_before = wbase[w] + rank;
    int pos = m ? obs_before : total + (tid - obs_before);
    g_obsidx[b*Nn + pos] = tid;
    if (tid < Dd) g_toksum[b*Dd + tid] = 0.f;
}

// ---- stage 1: h_mean for 16 tokens per block, fully packed f32x2 ----
__global__ __launch_bounds__(256) void kstage1(
    const float* __restrict__ x,
    const float* __restrict__ Wp,
    const float* __restrict__ bp,
    const float* __restrict__ W2){
    __shared__ __align__(16) u64 sxp[8][96];    // [tpair][col] packed (even tok lo, odd tok hi)
    __shared__ float sxs[16][Pp];               // per-token patch-column sums
    __shared__ __align__(16) u64 sG2[256][10];  // [j][tpair], pad 10, 16B-aligned rows
    __shared__ u64 sv2[8][Dd];                  // phase-C partial (upper j half)
    int tid = threadIdx.x;
    int bn0 = blockIdx.x*16;

    for (int idx = tid; idx < 8*Tt; idx += 256){
        int tp = idx/Tt, c = idx - tp*Tt;
        float lo = x[(bn0+2*tp  )*Tt + c] * g_maskf[bn0+2*tp];
        float hi = x[(bn0+2*tp+1)*Tt + c] * g_maskf[bn0+2*tp+1];
        u64 pk; PACK2(pk, lo, hi);
        sxp[tp][c] = pk;
    }
    __syncthreads();
    if (tid < 128){
        int t = tid >> 3, p = tid & 7;
        int tp = t >> 1, half = t & 1;
        float s = 0.f;
        #pragma unroll
        for (int l = 0; l < Ll; l++){
            u64 v = sxp[tp][l*Ss + p];
            s += half ? f2hi(v) : f2lo(v);
        }
        sxs[t][p] = s;
    }

    // phase B: packed u + packed gelu
    {
        int j = tid;
        u64 wf2[8];
        #pragma unroll
        for (int p = 0; p < 8; p++) PACKF2(wf2[p], g_wf[p*256 + j]);
        u64 ub2; PACKF2(ub2, g_wf[8*256 + j]);
        u64 C1P, C2P, HALFP;
        PACKF2(C1P, 0.035677408136f);
        PACKF2(C2P, 0.797884560803f);
        PACKF2(HALFP, 0.5f);
        #pragma unroll 1
        for (int tp = 0; tp < 8; tp++){
            const ulonglong2* xv = (const ulonglong2*)&sxp[tp][0];
            ulonglong2 A = xv[0], Bv = xv[1];
            u64 Gp = 0ull;
            #pragma unroll
            for (int l = 0; l < Ll; l++){
                ulonglong2 Cv = xv[2*l+2], Dv = xv[2*l+3];
                u64 u = ub2;
                FMA2(u, A.x,  wf2[0], u); FMA2(u, A.y,  wf2[1], u);
                FMA2(u, Bv.x, wf2[2], u); FMA2(u, Bv.y, wf2[3], u);
                FMA2(u, Cv.x, wf2[4], u); FMA2(u, Cv.y, wf2[5], u);
                FMA2(u, Dv.x, wf2[6], u); FMA2(u, Dv.y, wf2[7], u);
                // packed gelu: 0.5x(1+tanh(x*(c2 + c1 x^2)))
                u64 x2p; MUL2(x2p, u, u);
                u64 t1;  FMA2(t1, C1P, x2p, C2P);
                u64 zp;  MUL2(zp, u, t1);
                unsigned zl, zh; UNPACK2(zl, zh, zp);
                float tl = tanh_fast(__uint_as_float(zl));
                float th = tanh_fast(__uint_as_float(zh));
                u64 tpk; PACK2(tpk, tl, th);
                u64 hxp; MUL2(hxp, u, HALFP);
                u64 res; FMA2(res, hxp, tpk, hxp);
                ADD2(Gp, Gp, res);
                A = Cv; Bv = Dv;
            }
            sG2[j][tp] = Gp;
        }
    }
    __syncthreads();

    // phase C: hm[t][d] = (23*bp[d] + xs.Wp[:,d] + sum_j G[t][j] W2[j][d]) / 23
    {
        int d = tid & 127, h2 = tid >> 7;
        u64 acc[8];
        #pragma unroll
        for (int tp = 0; tp < 8; tp++) acc[tp] = 0ull;
        int j0 = h2*128;
        for (int j = j0; j < j0+128; j++){
            float w = W2[j*Dd + d];
            u64 w2; PACKF2(w2, w);
            const ulonglong2* gr = (const ulonglong2*)&sG2[j][0];
            ulonglong2 g01 = gr[0], g23 = gr[1], g45 = gr[2], g67 = gr[3];
            FMA2(acc[0], g01.x, w2, acc[0]); FMA2(acc[1], g01.y, w2, acc[1]);
            FMA2(acc[2], g23.x, w2, acc[2]); FMA2(acc[3], g23.y, w2, acc[3]);
            FMA2(acc[4], g45.x, w2, acc[4]); FMA2(acc[5], g45.y, w2, acc[5]);
            FMA2(acc[6], g67.x, w2, acc[6]); FMA2(acc[7], g67.y, w2, acc[7]);
        }
        if (h2){
            #pragma unroll
            for (int tp = 0; tp < 8; tp++) sv2[tp][d] = acc[tp];
        }
        __syncthreads();
        if (!h2){
            float bpd = 23.0f*bp[d];
            float wpc[8];
            #pragma unroll
            for (int p = 0; p < 8; p++) wpc[p] = Wp[p*Dd + d];
            #pragma unroll
            for (int tp = 0; tp < 8; tp++){
                u64 o = sv2[tp][d];
                float lo = f2lo(acc[tp]) + f2lo(o);
                float hi = f2hi(acc[tp]) + f2hi(o);
                int t0 = 2*tp;
                float hs0 = bpd, hs1 = bpd;
                #pragma unroll
                for (int p = 0; p < 8; p++){
                    hs0 += sxs[t0  ][p]*wpc[p];
                    hs1 += sxs[t0+1][p]*wpc[p];
                }
                g_hmean[(bn0+t0  )*Dd + d] = (hs0 + lo) * (1.0f/23.0f);
                g_hmean[(bn0+t0+1)*Dd + d] = (hs1 + hi) * (1.0f/23.0f);
            }
        }
    }
}

// ---- q/k/v: 16 tokens/block, 192 threads = 3 proj x 64 column-pairs ----
__global__ __launch_bounds__(192, 4) void kqkv(
    const float* __restrict__ Wq,
    const float* __restrict__ Wk,
    const float* __restrict__ Wv,
    const float* __restrict__ ve){
    __shared__ __align__(16) float tokT[Dd][20];   // [d][t], pad 20, 16B-aligned rows
    int tid = threadIdx.x;
    int b = blockIdx.x >> 4;
    int i0 = (blockIdx.x & 15) * 16;
    int n = g_nobs[b];
    for (int idx = tid; idx < 16*Dd; idx += 192){
        int t = idx >> 7, d = idx & 127;
        int i = i0 + t;
        float val = 0.f;
        if (i < n){
            int src = g_obsidx[b*Nn + i];
            val = g_hmean[(b*Nn + src)*Dd + d] + ve[src*Dd + d];
        }
        tokT[d][t] = val;
    }
    __syncthreads();
    if (tid < Dd){
        const float4* r = (const float4*)&tokT[tid][0];
        float4 a = r[0], b4 = r[1], c4 = r[2], d4 = r[3];
        float s = a.x+a.y+a.z+a.w + b4.x+b4.y+b4.z+b4.w
                + c4.x+c4.y+c4.z+c4.w + d4.x+d4.y+d4.z+d4.w;
        atomicAdd(&g_toksum[b*Dd + tid], s);
    }
    int which = tid >> 6;               // 0=q,1=k,2=v
    int c0 = (tid & 63) * 2;
    const float* W = (which == 0) ? Wq : (which == 1 ? Wk : Wv);
    float* dst = (which == 0) ? g_q : (which == 1 ? g_k : g_v);
    u64 a0[8], a1[8];
    #pragma unroll
    for (int r = 0; r < 8; r++){ a0[r] = 0ull; a1[r] = 0ull; }
    for (int d = 0; d < Dd; d++){
        float2 w = *(const float2*)&W[d*Dd + c0];
        u64 w2a, w2b;
        PACKF2(w2a, w.x);
        PACKF2(w2b, w.y);
        const ulonglong2* row = (const ulonglong2*)&tokT[d][0];
        ulonglong2 p0 = row[0], p1 = row[1], p2 = row[2], p3 = row[3];
        FMA2(a0[0], p0.x, w2a, a0[0]); FMA2(a1[0], p0.x, w2b, a1[0]);
        FMA2(a0[1], p0.y, w2a, a0[1]); FMA2(a1[1], p0.y, w2b, a1[1]);
        FMA2(a0[2], p1.x, w2a, a0[2]); FMA2(a1[2], p1.x, w2b, a1[2]);
        FMA2(a0[3], p1.y, w2a, a0[3]); FMA2(a1[3], p1.y, w2b, a1[3]);
        FMA2(a0[4], p2.x, w2a, a0[4]); FMA2(a1[4], p2.x, w2b, a1[4]);
        FMA2(a0[5], p2.y, w2a, a0[5]); FMA2(a1[5], p2.y, w2b, a1[5]);
        FMA2(a0[6], p3.x, w2a, a0[6]); FMA2(a1[6], p3.x, w2b, a1[6]);
        FMA2(a0[7], p3.y, w2a, a0[7]); FMA2(a1[7], p3.y, w2b, a1[7]);
    }
    #pragma unroll
    for (int r = 0; r < 8; r++){
        float2 e0 = make_float2(f2lo(a0[r]), f2lo(a1[r]));   // token 2r
        float2 e1 = make_float2(f2hi(a0[r]), f2hi(a1[r]));   // token 2r+1
        *(float2*)&dst[(b*Nn + i0 + 2*r    )*Dd + c0] = e0;
        *(float2*)&dst[(b*Nn + i0 + 2*r + 1)*Dd + c0] = e1;
    }
}

// ---- attention per (b,h): row-sum of attn@v == colsum(P) @ V ----
__global__ __launch_bounds__(256) void kattn(){
    __shared__ __align__(16) float ks[Nn][20];   // K rows, pad 20 -> conflict-free float4
    __shared__ float colsum[Nn];                 // sum over queries of prob columns
    __shared__ float psum[16][17];               // final matvec partials
    int b = blockIdx.x / Hh, h = blockIdx.x % Hh;
    int n = g_nobs[b];
    int tid = threadIdx.x;
    for (int idx = tid; idx < n*16; idx += 256){
        int jj = idx >> 4, c = idx & 15;
        ks[jj][c] = g_k[(b*Nn + jj)*Dd + h*16 + c];
    }
    for (int idx = tid; idx < Nn; idx += 256) colsum[idx] = 0.f;
    __syncthreads();
    int w = tid >> 5, lane = tid & 31;
    float cs[8];
    #pragma unroll
    for (int r = 0; r < 8; r++) cs[r] = 0.f;
    for (int i = w; i < n; i += 8){
        // broadcast q into registers
        float qv = (lane < 16) ? g_q[(b*Nn + i)*Dd + h*16 + lane] : 0.f;
        float qr[16];
        #pragma unroll
        for (int cc = 0; cc < 16; cc++) qr[cc] = __shfl_sync(0xffffffffu, qv, cc);
        float sc[8];
        float mx = -1e30f;
        #pragma unroll
        for (int r = 0; r < 8; r++){
            int jj = lane + 32*r;
            float s = -1e30f;
            if (jj < n){
                const float4* kr = (const float4*)&ks[jj][0];
                float4 k0 = kr[0], k1 = kr[1], k2 = kr[2], k3 = kr[3];
                s  = qr[0]*k0.x  + qr[1]*k0.y  + qr[2]*k0.z  + qr[3]*k0.w;
                s += qr[4]*k1.x  + qr[5]*k1.y  + qr[6]*k1.z  + qr[7]*k1.w;
                s += qr[8]*k2.x  + qr[9]*k2.y  + qr[10]*k2.z + qr[11]*k2.w;
                s += qr[12]*k3.x + qr[13]*k3.y + qr[14]*k3.z + qr[15]*k3.w;
                s *= 0.25f;
            }
            sc[r] = s;
            mx = fmaxf(mx, s);
        }
        #pragma unroll
        for (int off = 16; off; off >>= 1) mx = fmaxf(mx, __shfl_xor_sync(0xffffffffu, mx, off));
        float se = 0.f;
        #pragma unroll
        for (int r = 0; r < 8; r++){
            int jj = lane + 32*r;
            float p = (jj < n) ? __expf(sc[r] - mx) : 0.f;
            sc[r] = p; se += p;
        }
        #pragma unroll
        for (int off = 16; off; off >>= 1) se += __shfl_xor_sync(0xffffffffu, se, off);
        float inv = __fdividef(1.0f, se);
        #pragma unroll
        for (int r = 0; r < 8; r++) cs[r] += sc[r]*inv;
    }
    // merge per-warp colsums (lane's jj fixed = lane + 32r)
    #pragma unroll
    for (int r = 0; r < 8; r++){
        int jj = lane + 32*r;
        atomicAdd(&colsum[jj], cs[r]);
    }
    __syncthreads();
    // attnsum[c] = sum_j colsum[j] * v[j][c]
    {
        int c = tid & 15, g = tid >> 4;   // 16 groups x 16 cols
        float acc = 0.f;
        for (int j = g; j < n; j += 16)
            acc += colsum[j] * g_v[(b*Nn + j)*Dd + h*16 + c];
        psum[g][c] = acc;
        __syncthreads();
        if (tid < 16){
            float s = 0.f;
            #pragma unroll
            for (int gg = 0; gg < 16; gg++) s += psum[gg][tid];
            g_attnsum[b*Dd + h*16 + tid] = s;
        }
    }
}

// ---- per-batch: epilogue (Q_sub/w_sub/conf/fill) + y_hat for all 256 tokens ----
__global__ __launch_bounds__(256) void kfinaly(
    const float* __restrict__ Wo,
    const float* __restrict__ C,
    const float* __restrict__ Wdec,
    const float* __restrict__ Wh,
    float* __restrict__ y,
    float* __restrict__ outQ,
    float* __restrict__ outW,
    float* __restrict__ outC){
    __shared__ float sa[Dd], Qs[Dd], lg[Kk], wk[Kk], zc[Dd], saf[Dd];
    __shared__ float s_alpha, s_conf;
    __shared__ __align__(16) float sWhT[PLl][132];
    __shared__ __align__(16) float E[8][Dd];
    int b = blockIdx.x, tid = threadIdx.x;
    int n = g_nobs[b];
    // load transposed head weights
    for (int idx = tid; idx < Dd*PLl; idx += 256){
        int d = idx / PLl, pl = idx - d*PLl;
        sWhT[pl][d] = Wh[idx];
    }
    if (tid < Dd) sa[tid] = g_attnsum[b*Dd + tid];
    __syncthreads();
    if (tid < Dd){
        float q = 0.f;
        #pragma unroll 4
        for (int jj = 0; jj < Dd; jj++) q += sa[jj]*Wo[jj*Dd + tid];
        q = (q + g_toksum[b*Dd + tid])/(float)n;
        Qs[tid] = q;
        if (outQ) outQ[b*Dd + tid] = q;
    }
    __syncthreads();
    if (tid < Kk){
        float lgv = 0.f;
        #pragma unroll 4
        for (int dd = 0; dd < Dd; dd++) lgv += Qs[dd]*C[tid*Dd + dd];
        lg[tid] = lgv * 2.0f;
    }
    __syncthreads();
    if (tid == 0){
        float mx = -1e30f;
        for (int k = 0; k < Kk; k++) mx = fmaxf(mx, lg[k]);
        float s = 0.f;
        for (int k = 0; k < Kk; k++){ wk[k] = expf(lg[k]-mx); s += wk[k]; }
        float inv = 1.0f/s, wmax = 0.f;
        for (int k = 0; k < Kk; k++){ wk[k] *= inv; wmax = fmaxf(wmax, wk[k]); }
        float conf = wmax * ((float)n/(float)Nn);
        s_conf = conf;
        s_alpha = 0.1f + 0.9f*conf;
        if (outC) outC[b] = conf;
    }
    __syncthreads();
    if (tid < Dd){
        float z = 0.f;
        #pragma unroll
        for (int k = 0; k < Kk; k++) z += wk[k]*C[k*Dd + tid];
        zc[tid] = z;
        if (outW && tid < Kk) outW[b*Kk + tid] = wk[tid];
    }
    __syncthreads();
    if (tid < Dd){
        float f = 0.f;
        #pragma unroll 4
        for (int jj = 0; jj < Dd; jj++) f += zc[jj]*Wdec[jj*Dd + tid];
        saf[tid] = s_alpha * f;
    }
    __syncthreads();
    // y_hat for this batch's 256 tokens, 8-token tiles
    for (int tt = 0; tt < 32; tt++){
        int bn0 = b*Nn + tt*8;
        for (int idx = tid; idx < 8*Dd; idx += 256){
            int t = idx >> 7, d = idx & 127;
            float m = g_maskf[bn0+t];
            E[t][d] = g_hmean[(bn0+t)*Dd + d] + (1.0f - m)*saf[d];
        }
        __syncthreads();
        if (tid < 192){
            int t = tid / PLl, pl = tid - t*PLl;
            float acc = 0.f;
            const float4* ev = (const float4*)&E[t][0];
            const float4* wv = (const float4*)&sWhT[pl][0];
            #pragma unroll 8
            for (int d4 = 0; d4 < Dd/4; d4++){
                float4 e = ev[d4], w = wv[d4];
                acc += e.x*w.x + e.y*w.y + e.z*w.z + e.w*w.w;
            }
            y[(bn0+t)*PLl + pl] = acc;
        }
        __syncthreads();
    }
}

extern "C" void kernel_launch(void* const* d_in, const int* in_sizes, int n_in,
                              void* d_out, int out_size){
    const float* x    = (const float*)d_in[0];
    const void*  mask = d_in[1];
    const float* Wp   = (const float*)d_in[2];
    const float* bp   = (const float*)d_in[3];
    const float* W1   = (const float*)d_in[4];
    const float* W2   = (const float*)d_in[5];
    const float* ve   = (const float*)d_in[6];
    const float* Wq   = (const float*)d_in[7];
    const float* Wk   = (const float*)d_in[8];
    const float* Wv   = (const float*)d_in[9];
    const float* Wo   = (const float*)d_in[10];
    const float* C    = (const float*)d_in[11];
    const float* Wdec = (const float*)d_in[12];
    const float* Wh   = (const float*)d_in[13];

    float* out = (float*)d_out;
    const int SZ_Y = Bb*Nn*PLl;
    const int SZ_Q = Bb*Dd;
    const int SZ_W = Bb*Kk;
    float* oy = out;
    float* oq = (out_size >= SZ_Y + SZ_Q)              ? out + SZ_Y                : nullptr;
    float* ow = (out_size >= SZ_Y + SZ_Q + SZ_W)       ? out + SZ_Y + SZ_Q         : nullptr;
    float* oc = (out_size >= SZ_Y + SZ_Q + SZ_W + Bb)  ? out + SZ_Y + SZ_Q + SZ_W  : nullptr;

    kmaskfold<<<Bb+1, 256>>>((const unsigned char*)mask, Wp, bp, W1);
    kstage1<<<Bb*Nn/16, 256>>>(x, Wp, bp, W2);
    kqkv<<<Bb*Nn/16, 192>>>(Wq, Wk, Wv, ve);
    kattn<<<Bb*Hh, 256>>>();
    kfinaly<<<Bb, 256>>>(Wo, C, Wdec, Wh, oy, oq, ow, oc);
}

// round 10
// speedup vs baseline: 4.4300x; 1.1324x over previous
#include <cuda_runtime.h>
#include <math.h>

// ---- problem constants ----
#define Bb 64
#define Nn 256
#define Tt 96
#define Pp 8
#define Ss 4
#define Dd 128
#define Hh 8
#define Kk 16
#define PLl 24
#define Ll 23

// ---- scratch ----
__device__ float g_maskf[Bb*Nn];
__device__ float g_wf[9*256];          // rows 0..7: (Wp@W1)[p][j]; row 8: bp@W1
__device__ __align__(16) float g_hmean[Bb*Nn*Dd];
__device__ int   g_obsidx[Bb*Nn];
__device__ int   g_nobs[Bb];
__device__ __align__(16) float g_q[Bb*Nn*Dd];
__device__ __align__(16) float g_k[Bb*Nn*Dd];
__device__ __align__(16) float g_v[Bb*Nn*Dd];
__device__ float g_attnsum[Bb*Dd];
__device__ float g_toksum[Bb*Dd];
__device__ float g_afill[Bb*Dd];

typedef unsigned long long u64;

#define FMA2(d,a,b,c) asm("fma.rn.f32x2 %0, %1, %2, %3;" : "=l"(d) : "l"(a), "l"(b), "l"(c))
#define MUL2(d,a,b)   asm("mul.rn.f32x2 %0, %1, %2;" : "=l"(d) : "l"(a), "l"(b))
#define ADD2(d,a,b)   asm("add.rn.f32x2 %0, %1, %2;" : "=l"(d) : "l"(a), "l"(b))
#define PACKF2(o,f)   asm("mov.b64 %0, {%1, %1};" : "=l"(o) : "r"(__float_as_uint(f)))
#define PACK2(o,a,b)  asm("mov.b64 %0, {%1, %2};" : "=l"(o) : "r"(__float_as_uint(a)), "r"(__float_as_uint(b)))
#define UNPACK2(a,b,i) asm("mov.b64 {%0, %1}, %2;" : "=r"(a), "=r"(b) : "l"(i))

__device__ __forceinline__ float f2lo(u64 v){ return __uint_as_float((unsigned)(v & 0xffffffffull)); }
__device__ __forceinline__ float f2hi(u64 v){ return __uint_as_float((unsigned)(v >> 32)); }

__device__ __forceinline__ float tanh_fast(float z){
    float t;
    asm("tanh.approx.f32 %0, %1;" : "=f"(t) : "f"(z));
    return t;
}

// ---- fused: blocks 0..63 = mask decode + compaction (per-block dtype sniff);
//             block 64 = fold Wp/bp into W1 ----
__global__ __launch_bounds__(256) void kmaskfold(const unsigned char* __restrict__ mp,
                                                 const float* __restrict__ Wp,
                                                 const float* __restrict__ bp,
                                                 const float* __restrict__ W1){
    int tid = threadIdx.x;
    if (blockIdx.x == Bb){
        __shared__ float sWp[Pp*Dd];
        __shared__ float sbp[Dd];
        for (int i = tid; i < Pp*Dd; i += 256) sWp[i] = Wp[i];
        if (tid < Dd) sbp[tid] = bp[tid];
        __syncthreads();
        int j = tid;
        float acc[9];
        #pragma unroll
        for (int p = 0; p < 9; p++) acc[p] = 0.f;
        for (int d = 0; d < Dd; d++){
            float w1 = W1[d*256 + j];
            #pragma unroll
            for (int p = 0; p < 8; p++) acc[p] += sWp[p*Dd + d]*w1;
            acc[8] += sbp[d]*w1;
        }
        #pragma unroll
        for (int p = 0; p < 9; p++) g_wf[p*256 + j] = acc[p];
        return;
    }
    __shared__ int sawF, sawB;
    __shared__ int wtot[8];
    __shared__ int wbase[9];
    if (tid == 0){ sawF = 0; sawB = 0; }
    __syncthreads();
    for (int i = tid; i < Bb*Nn; i += 256){
        unsigned char c = mp[i];
        if (c == 0x3f || c == 0x80) sawF = 1;
        else if (c != 0 && (i & 3) != 0) sawB = 1;
    }
    __syncthreads();
    int mode = sawF ? 0 : (sawB ? 2 : 1);
    int b = blockIdx.x;
    int i = b*Nn + tid;
    bool m;
    if (mode == 0)      m = ((const float*)mp)[i] != 0.0f;
    else if (mode == 1) m = ((const int*)mp)[i]   != 0;
    else                m = mp[i] != 0;
    g_maskf[i] = m ? 1.0f : 0.0f;
    unsigned bits = __ballot_sync(0xffffffffu, m);
    int w = tid >> 5, lane = tid & 31;
    int rank = __popc(bits & ((1u << lane) - 1u));
    if (lane == 0) wtot[w] = __popc(bits);
    __syncthreads();
    if (tid == 0){
        int s = 0;
        #pragma unroll
        for (int ww = 0; ww < 8; ww++){ wbase[ww] = s; s += wtot[ww]; }
        wbase[8] = s;
        g_nobs[b] = s;
    }
    __syncthreads();
    int total = wbase[8];
    int obs_before = wbase[w] + rank;
    int pos = m ? obs_before : total + (tid - obs_before);
    g_obsidx[b*Nn + pos] = tid;
    if (tid < Dd) g_toksum[b*Dd + tid] = 0.f;
}

// ---- stage 1: h_mean for 16 tokens per block, fully packed f32x2 ----
__global__ __launch_bounds__(256) void kstage1(
    const float* __restrict__ x,
    const float* __restrict__ Wp,
    const float* __restrict__ bp,
    const float* __restrict__ W2){
    __shared__ __align__(16) u64 sxp[8][96];
    __shared__ float sxs[16][Pp];
    __shared__ __align__(16) u64 sG2[256][10];
    __shared__ u64 sv2[8][Dd];
    int tid = threadIdx.x;
    int bn0 = blockIdx.x*16;

    for (int idx = tid; idx < 8*Tt; idx += 256){
        int tp = idx/Tt, c = idx - tp*Tt;
        float lo = x[(bn0+2*tp  )*Tt + c] * g_maskf[bn0+2*tp];
        float hi = x[(bn0+2*tp+1)*Tt + c] * g_maskf[bn0+2*tp+1];
        u64 pk; PACK2(pk, lo, hi);
        sxp[tp][c] = pk;
    }
    __syncthreads();
    if (tid < 128){
        int t = tid >> 3, p = tid & 7;
        int tp = t >> 1, half = t & 1;
        float s = 0.f;
        #pragma unroll
        for (int l = 0; l < Ll; l++){
            u64 v = sxp[tp][l*Ss + p];
            s += half ? f2hi(v) : f2lo(v);
        }
        sxs[t][p] = s;
    }

    {
        int j = tid;
        u64 wf2[8];
        #pragma unroll
        for (int p = 0; p < 8; p++) PACKF2(wf2[p], g_wf[p*256 + j]);
        u64 ub2; PACKF2(ub2, g_wf[8*256 + j]);
        u64 C1P, C2P, HALFP;
        PACKF2(C1P, 0.035677408136f);
        PACKF2(C2P, 0.797884560803f);
        PACKF2(HALFP, 0.5f);
        #pragma unroll 1
        for (int tp = 0; tp < 8; tp++){
            const ulonglong2* xv = (const ulonglong2*)&sxp[tp][0];
            ulonglong2 A = xv[0], Bv = xv[1];
            u64 Gp = 0ull;
            #pragma unroll
            for (int l = 0; l < Ll; l++){
                ulonglong2 Cv = xv[2*l+2], Dv = xv[2*l+3];
                u64 u = ub2;
                FMA2(u, A.x,  wf2[0], u); FMA2(u, A.y,  wf2[1], u);
                FMA2(u, Bv.x, wf2[2], u); FMA2(u, Bv.y, wf2[3], u);
                FMA2(u, Cv.x, wf2[4], u); FMA2(u, Cv.y, wf2[5], u);
                FMA2(u, Dv.x, wf2[6], u); FMA2(u, Dv.y, wf2[7], u);
                u64 x2p; MUL2(x2p, u, u);
                u64 t1;  FMA2(t1, C1P, x2p, C2P);
                u64 zp;  MUL2(zp, u, t1);
                unsigned zl, zh; UNPACK2(zl, zh, zp);
                float tl = tanh_fast(__uint_as_float(zl));
                float th = tanh_fast(__uint_as_float(zh));
                u64 tpk; PACK2(tpk, tl, th);
                u64 hxp; MUL2(hxp, u, HALFP);
                u64 res; FMA2(res, hxp, tpk, hxp);
                ADD2(Gp, Gp, res);
                A = Cv; Bv = Dv;
            }
            sG2[j][tp] = Gp;
        }
    }
    __syncthreads();

    {
        int d = tid & 127, h2 = tid >> 7;
        u64 acc[8];
        #pragma unroll
        for (int tp = 0; tp < 8; tp++) acc[tp] = 0ull;
        int j0 = h2*128;
        for (int j = j0; j < j0+128; j++){
            float w = W2[j*Dd + d];
            u64 w2; PACKF2(w2, w);
            const ulonglong2* gr = (const ulonglong2*)&sG2[j][0];
            ulonglong2 g01 = gr[0], g23 = gr[1], g45 = gr[2], g67 = gr[3];
            FMA2(acc[0], g01.x, w2, acc[0]); FMA2(acc[1], g01.y, w2, acc[1]);
            FMA2(acc[2], g23.x, w2, acc[2]); FMA2(acc[3], g23.y, w2, acc[3]);
            FMA2(acc[4], g45.x, w2, acc[4]); FMA2(acc[5], g45.y, w2, acc[5]);
            FMA2(acc[6], g67.x, w2, acc[6]); FMA2(acc[7], g67.y, w2, acc[7]);
        }
        if (h2){
            #pragma unroll
            for (int tp = 0; tp < 8; tp++) sv2[tp][d] = acc[tp];
        }
        __syncthreads();
        if (!h2){
            float bpd = 23.0f*bp[d];
            float wpc[8];
            #pragma unroll
            for (int p = 0; p < 8; p++) wpc[p] = Wp[p*Dd + d];
            #pragma unroll
            for (int tp = 0; tp < 8; tp++){
                u64 o = sv2[tp][d];
                float lo = f2lo(acc[tp]) + f2lo(o);
                float hi = f2hi(acc[tp]) + f2hi(o);
                int t0 = 2*tp;
                float hs0 = bpd, hs1 = bpd;
                #pragma unroll
                for (int p = 0; p < 8; p++){
                    hs0 += sxs[t0  ][p]*wpc[p];
                    hs1 += sxs[t0+1][p]*wpc[p];
                }
                g_hmean[(bn0+t0  )*Dd + d] = (hs0 + lo) * (1.0f/23.0f);
                g_hmean[(bn0+t0+1)*Dd + d] = (hs1 + hi) * (1.0f/23.0f);
            }
        }
    }
}

// ---- q/k/v: 16 tokens/block, 192 threads = 3 proj x 64 column-pairs ----
__global__ __launch_bounds__(192, 4) void kqkv(
    const float* __restrict__ Wq,
    const float* __restrict__ Wk,
    const float* __restrict__ Wv,
    const float* __restrict__ ve){
    __shared__ __align__(16) float tokT[Dd][20];
    int tid = threadIdx.x;
    int b = blockIdx.x >> 4;
    int i0 = (blockIdx.x & 15) * 16;
    int n = g_nobs[b];
    for (int idx = tid; idx < 16*Dd; idx += 192){
        int t = idx >> 7, d = idx & 127;
        int i = i0 + t;
        float val = 0.f;
        if (i < n){
            int src = g_obsidx[b*Nn + i];
            val = g_hmean[(b*Nn + src)*Dd + d] + ve[src*Dd + d];
        }
        tokT[d][t] = val;
    }
    __syncthreads();
    if (tid < Dd){
        const float4* r = (const float4*)&tokT[tid][0];
        float4 a = r[0], b4 = r[1], c4 = r[2], d4 = r[3];
        float s = a.x+a.y+a.z+a.w + b4.x+b4.y+b4.z+b4.w
                + c4.x+c4.y+c4.z+c4.w + d4.x+d4.y+d4.z+d4.w;
        atomicAdd(&g_toksum[b*Dd + tid], s);
    }
    int which = tid >> 6;
    int c0 = (tid & 63) * 2;
    const float* W = (which == 0) ? Wq : (which == 1 ? Wk : Wv);
    float* dst = (which == 0) ? g_q : (which == 1 ? g_k : g_v);
    u64 a0[8], a1[8];
    #pragma unroll
    for (int r = 0; r < 8; r++){ a0[r] = 0ull; a1[r] = 0ull; }
    for (int d = 0; d < Dd; d++){
        float2 w = *(const float2*)&W[d*Dd + c0];
        u64 w2a, w2b;
        PACKF2(w2a, w.x);
        PACKF2(w2b, w.y);
        const ulonglong2* row = (const ulonglong2*)&tokT[d][0];
        ulonglong2 p0 = row[0], p1 = row[1], p2 = row[2], p3 = row[3];
        FMA2(a0[0], p0.x, w2a, a0[0]); FMA2(a1[0], p0.x, w2b, a1[0]);
        FMA2(a0[1], p0.y, w2a, a0[1]); FMA2(a1[1], p0.y, w2b, a1[1]);
        FMA2(a0[2], p1.x, w2a, a0[2]); FMA2(a1[2], p1.x, w2b, a1[2]);
        FMA2(a0[3], p1.y, w2a, a0[3]); FMA2(a1[3], p1.y, w2b, a1[3]);
        FMA2(a0[4], p2.x, w2a, a0[4]); FMA2(a1[4], p2.x, w2b, a1[4]);
        FMA2(a0[5], p2.y, w2a, a0[5]); FMA2(a1[5], p2.y, w2b, a1[5]);
        FMA2(a0[6], p3.x, w2a, a0[6]); FMA2(a1[6], p3.x, w2b, a1[6]);
        FMA2(a0[7], p3.y, w2a, a0[7]); FMA2(a1[7], p3.y, w2b, a1[7]);
    }
    #pragma unroll
    for (int r = 0; r < 8; r++){
        float2 e0 = make_float2(f2lo(a0[r]), f2lo(a1[r]));
        float2 e1 = make_float2(f2hi(a0[r]), f2hi(a1[r]));
        *(float2*)&dst[(b*Nn + i0 + 2*r    )*Dd + c0] = e0;
        *(float2*)&dst[(b*Nn + i0 + 2*r + 1)*Dd + c0] = e1;
    }
}

// ---- attention per (b,h): 4 queries/iter, packed f32x2 scores ----
__global__ __launch_bounds__(256) void kattn(){
    __shared__ __align__(16) float ks[Nn][20];   // stride-20 rows: conflict-free LDS.128
    __shared__ __align__(16) float qs[Nn][16];   // broadcast reads only
    __shared__ float colsum[Nn];
    __shared__ float psum[16][17];
    int b = blockIdx.x >> 3, h = blockIdx.x & 7;
    int n = g_nobs[b];
    int tid = threadIdx.x;
    for (int idx = tid; idx < Nn*16; idx += 256){
        int jj = idx >> 4, c = idx & 15;
        float kv = 0.f, qv = 0.f;
        if (jj < n){
            kv = g_k[(b*Nn + jj)*Dd + h*16 + c];
            qv = g_q[(b*Nn + jj)*Dd + h*16 + c];
        }
        ks[jj][c] = kv;
        qs[jj][c] = qv;
    }
    for (int idx = tid; idx < Nn; idx += 256) colsum[idx] = 0.f;
    __syncthreads();
    int w = tid >> 5, lane = tid & 31;
    float cs[8];
    #pragma unroll
    for (int r = 0; r < 8; r++) cs[r] = 0.f;
    for (int i0 = w*4; i0 < n; i0 += 32){
        // pack q columns for query pairs (i0,i0+1) and (i0+2,i0+3); i0<=252 so rows in-bounds
        u64 qp01[16], qp23[16];
        #pragma unroll
        for (int c = 0; c < 16; c++){
            PACK2(qp01[c], qs[i0  ][c], qs[i0+1][c]);
            PACK2(qp23[c], qs[i0+2][c], qs[i0+3][c]);
        }
        u64 s01[8], s23[8];
        #pragma unroll
        for (int r = 0; r < 8; r++){
            int jj = lane + 32*r;
            const float4* kr = (const float4*)&ks[jj][0];
            float4 k0 = kr[0], k1 = kr[1], k2 = kr[2], k3 = kr[3];
            u64 a = 0ull, bb = 0ull, kp;
            PACKF2(kp, k0.x); FMA2(a, qp01[0],  kp, a); FMA2(bb, qp23[0],  kp, bb);
            PACKF2(kp, k0.y); FMA2(a, qp01[1],  kp, a); FMA2(bb, qp23[1],  kp, bb);
            PACKF2(kp, k0.z); FMA2(a, qp01[2],  kp, a); FMA2(bb, qp23[2],  kp, bb);
            PACKF2(kp, k0.w); FMA2(a, qp01[3],  kp, a); FMA2(bb, qp23[3],  kp, bb);
            PACKF2(kp, k1.x); FMA2(a, qp01[4],  kp, a); FMA2(bb, qp23[4],  kp, bb);
            PACKF2(kp, k1.y); FMA2(a, qp01[5],  kp, a); FMA2(bb, qp23[5],  kp, bb);
            PACKF2(kp, k1.z); FMA2(a, qp01[6],  kp, a); FMA2(bb, qp23[6],  kp, bb);
            PACKF2(kp, k1.w); FMA2(a, qp01[7],  kp, a); FMA2(bb, qp23[7],  kp, bb);
            PACKF2(kp, k2.x); FMA2(a, qp01[8],  kp, a); FMA2(bb, qp23[8],  kp, bb);
            PACKF2(kp, k2.y); FMA2(a, qp01[9],  kp, a); FMA2(bb, qp23[9],  kp, bb);
            PACKF2(kp, k2.z); FMA2(a, qp01[10], kp, a); FMA2(bb, qp23[10], kp, bb);
            PACKF2(kp, k2.w); FMA2(a, qp01[11], kp, a); FMA2(bb, qp23[11], kp, bb);
            PACKF2(kp, k3.x); FMA2(a, qp01[12], kp, a); FMA2(bb, qp23[12], kp, bb);
            PACKF2(kp, k3.y); FMA2(a, qp01[13], kp, a); FMA2(bb, qp23[13], kp, bb);
            PACKF2(kp, k3.z); FMA2(a, qp01[14], kp, a); FMA2(bb, qp23[14], kp, bb);
            PACKF2(kp, k3.w); FMA2(a, qp01[15], kp, a); FMA2(bb, qp23[15], kp, bb);
            s01[r] = a; s23[r] = bb;
        }
        // softmax per query, accumulate colsum contributions
        #pragma unroll
        for (int qi = 0; qi < 4; qi++){
            float sq[8];
            #pragma unroll
            for (int r = 0; r < 8; r++){
                u64 v = (qi < 2) ? s01[r] : s23[r];
                float raw = (qi & 1) ? f2hi(v) : f2lo(v);
                int jj = lane + 32*r;
                sq[r] = (jj < n) ? raw*0.25f : -1e30f;
            }
            float mx = sq[0];
            #pragma unroll
            for (int r = 1; r < 8; r++) mx = fmaxf(mx, sq[r]);
            #pragma unroll
            for (int off = 16; off; off >>= 1) mx = fmaxf(mx, __shfl_xor_sync(0xffffffffu, mx, off));
            float se = 0.f;
            #pragma unroll
            for (int r = 0; r < 8; r++){
                sq[r] = __expf(sq[r] - mx);
                se += sq[r];
            }
            #pragma unroll
            for (int off = 16; off; off >>= 1) se += __shfl_xor_sync(0xffffffffu, se, off);
            float inv = (i0 + qi < n) ? __fdividef(1.0f, se) : 0.f;
            #pragma unroll
            for (int r = 0; r < 8; r++) cs[r] += sq[r]*inv;
        }
    }
    #pragma unroll
    for (int r = 0; r < 8; r++){
        int jj = lane + 32*r;
        atomicAdd(&colsum[jj], cs[r]);
    }
    __syncthreads();
    {
        int c = tid & 15, g = tid >> 4;
        float acc = 0.f;
        for (int j = g; j < n; j += 16)
            acc += colsum[j] * g_v[(b*Nn + j)*Dd + h*16 + c];
        psum[g][c] = acc;
        __syncthreads();
        if (tid < 16){
            float s = 0.f;
            #pragma unroll
            for (int gg = 0; gg < 16; gg++) s += psum[gg][tid];
            g_attnsum[b*Dd + h*16 + tid] = s;
        }
    }
}

// ---- per-batch epilogue: Q_sub, w_sub, conf, alpha*fill ----
__global__ __launch_bounds__(128) void kfinal(
    const float* __restrict__ Wo,
    const float* __restrict__ C,
    const float* __restrict__ Wdec,
    float* __restrict__ outQ,
    float* __restrict__ outW,
    float* __restrict__ outC){
    __shared__ float sa[Dd], Qs[Dd], lg[Kk], wk[Kk], zc[Dd];
    __shared__ float s_alpha, s_conf;
    int b = blockIdx.x, d = threadIdx.x;
    int n = g_nobs[b];
    sa[d] = g_attnsum[b*Dd + d];
    __syncthreads();
    float q = 0.f;
    #pragma unroll 4
    for (int jj = 0; jj < Dd; jj++) q += sa[jj]*Wo[jj*Dd + d];
    q = (q + g_toksum[b*Dd + d])/(float)n;
    Qs[d] = q;
    __syncthreads();
    if (d < Kk){
        float lgv = 0.f;
        #pragma unroll 4
        for (int dd = 0; dd < Dd; dd++) lgv += Qs[dd]*C[d*Dd + dd];
        lg[d] = lgv * 2.0f;
    }
    __syncthreads();
    if (d == 0){
        float mx = -1e30f;
        for (int k = 0; k < Kk; k++) mx = fmaxf(mx, lg[k]);
        float s = 0.f;
        for (int k = 0; k < Kk; k++){ wk[k] = expf(lg[k]-mx); s += wk[k]; }
        float inv = 1.0f/s, wmax = 0.f;
        for (int k = 0; k < Kk; k++){ wk[k] *= inv; wmax = fmaxf(wmax, wk[k]); }
        float conf = wmax * ((float)n/(float)Nn);
        s_conf = conf;
        s_alpha = 0.1f + 0.9f*conf;
        if (outC) outC[b] = conf;
    }
    __syncthreads();
    float z = 0.f;
    #pragma unroll
    for (int k = 0; k < Kk; k++) z += wk[k]*C[k*Dd + d];
    zc[d] = z;
    __syncthreads();
    float f = 0.f;
    #pragma unroll 4
    for (int jj = 0; jj < Dd; jj++) f += zc[jj]*Wdec[jj*Dd + d];
    g_afill[b*Dd + d] = s_alpha * f;
    if (outQ) outQ[b*Dd + d] = q;
    if (outW && d < Kk) outW[b*Kk + d] = wk[d];
}

// ---- y_hat, 8 tokens per block ----
__global__ __launch_bounds__(256) void kyhat(
    const float* __restrict__ Wh,
    float* __restrict__ y){
    __shared__ __align__(16) float E[8][Dd];
    __shared__ __align__(16) float sWhT[PLl][132];
    int tid = threadIdx.x;
    int bn0 = blockIdx.x*8;
    int b = bn0 >> 8;
    for (int idx = tid; idx < 8*Dd; idx += 256){
        int t = idx >> 7, d = idx & 127;
        float m = g_maskf[bn0+t];
        E[t][d] = g_hmean[(bn0+t)*Dd + d] + (1.0f - m)*g_afill[b*Dd + d];
    }
    for (int idx = tid; idx < Dd*PLl; idx += 256){
        int d = idx / PLl, pl = idx - d*PLl;
        sWhT[pl][d] = Wh[idx];
    }
    __syncthreads();
    if (tid < 192){
        int t = tid / PLl, pl = tid - t*PLl;
        float acc = 0.f;
        const float4* ev = (const float4*)&E[t][0];
        const float4* wv = (const float4*)&sWhT[pl][0];
        #pragma unroll 8
        for (int d4 = 0; d4 < Dd/4; d4++){
            float4 e = ev[d4], w = wv[d4];
            acc += e.x*w.x + e.y*w.y + e.z*w.z + e.w*w.w;
        }
        y[(bn0+t)*PLl + pl] = acc;
    }
}

extern "C" void kernel_launch(void* const* d_in, const int* in_sizes, int n_in,
                              void* d_out, int out_size){
    const float* x    = (const float*)d_in[0];
    const void*  mask = d_in[1];
    const float* Wp   = (const float*)d_in[2];
    const float* bp   = (const float*)d_in[3];
    const float* W1   = (const float*)d_in[4];
    const float* W2   = (const float*)d_in[5];
    const float* ve   = (const float*)d_in[6];
    const float* Wq   = (const float*)d_in[7];
    const float* Wk   = (const float*)d_in[8];
    const float* Wv   = (const float*)d_in[9];
    const float* Wo   = (const float*)d_in[10];
    const float* C    = (const float*)d_in[11];
    const float* Wdec = (const float*)d_in[12];
    const float* Wh   = (const float*)d_in[13];

    float* out = (float*)d_out;
    const int SZ_Y = Bb*Nn*PLl;
    const int SZ_Q = Bb*Dd;
    const int SZ_W = Bb*Kk;
    float* oy = out;
    float* oq = (out_size >= SZ_Y + SZ_Q)              ? out + SZ_Y                : nullptr;
    float* ow = (out_size >= SZ_Y + SZ_Q + SZ_W)       ? out + SZ_Y + SZ_Q         : nullptr;
    float* oc = (out_size >= SZ_Y + SZ_Q + SZ_W + Bb)  ? out + SZ_Y + SZ_Q + SZ_W  : nullptr;

    kmaskfold<<<Bb+1, 256>>>((const unsigned char*)mask, Wp, bp, W1);
    kstage1<<<Bb*Nn/16, 256>>>(x, Wp, bp, W2);
    kqkv<<<Bb*Nn/16, 192>>>(Wq, Wk, Wv, ve);
    kattn<<<Bb*Hh, 256>>>();
    kfinal<<<Bb, Dd>>>(Wo, C, Wdec, oq, ow, oc);
    kyhat<<<Bb*Nn/8, 256>>>(Wh, oy);
}

// round 11
// speedup vs baseline: 4.4721x; 1.0095x over previous
#include <cuda_runtime.h>
#include <math.h>

// ---- problem constants ----
#define Bb 64
#define Nn 256
#define Tt 96
#define Pp 8
#define Ss 4
#define Dd 128
#define Hh 8
#define Kk 16
#define PLl 24
#define Ll 23

// ---- scratch ----
__device__ float g_maskf[Bb*Nn];
__device__ float g_wf[9*256];          // rows 0..7: (Wp@W1)[p][j]; row 8: bp@W1
__device__ __align__(16) float g_hmean[Bb*Nn*Dd];
__device__ int   g_obsidx[Bb*Nn];
__device__ int   g_nobs[Bb];
__device__ __align__(16) float g_q[Bb*Nn*Dd];
__device__ __align__(16) float g_k[Bb*Nn*Dd];
__device__ __align__(16) float g_v[Bb*Nn*Dd];
__device__ float g_attnsum[Bb*Dd];
__device__ float g_toksum[Bb*Dd];
__device__ float g_afill[Bb*Dd];

typedef unsigned long long u64;

#define FMA2(d,a,b,c) asm("fma.rn.f32x2 %0, %1, %2, %3;" : "=l"(d) : "l"(a), "l"(b), "l"(c))
#define MUL2(d,a,b)   asm("mul.rn.f32x2 %0, %1, %2;" : "=l"(d) : "l"(a), "l"(b))
#define ADD2(d,a,b)   asm("add.rn.f32x2 %0, %1, %2;" : "=l"(d) : "l"(a), "l"(b))
#define PACKF2(o,f)   asm("mov.b64 %0, {%1, %1};" : "=l"(o) : "r"(__float_as_uint(f)))
#define PACK2(o,a,b)  asm("mov.b64 %0, {%1, %2};" : "=l"(o) : "r"(__float_as_uint(a)), "r"(__float_as_uint(b)))
#define UNPACK2(a,b,i) asm("mov.b64 {%0, %1}, %2;" : "=r"(a), "=r"(b) : "l"(i))

__device__ __forceinline__ float f2lo(u64 v){ return __uint_as_float((unsigned)(v & 0xffffffffull)); }
__device__ __forceinline__ float f2hi(u64 v){ return __uint_as_float((unsigned)(v >> 32)); }

__device__ __forceinline__ float tanh_fast(float z){
    float t;
    asm("tanh.approx.f32 %0, %1;" : "=f"(t) : "f"(z));
    return t;
}

// ---- fused: blocks 0..63 = mask decode + compaction (per-block dtype sniff);
//             block 64 = fold Wp/bp into W1 ----
__global__ __launch_bounds__(256) void kmaskfold(const unsigned char* __restrict__ mp,
                                                 const float* __restrict__ Wp,
                                                 const float* __restrict__ bp,
                                                 const float* __restrict__ W1){
    int tid = threadIdx.x;
    if (blockIdx.x == Bb){
        __shared__ float sWp[Pp*Dd];
        __shared__ float sbp[Dd];
        for (int i = tid; i < Pp*Dd; i += 256) sWp[i] = Wp[i];
        if (tid < Dd) sbp[tid] = bp[tid];
        __syncthreads();
        int j = tid;
        float acc[9];
        #pragma unroll
        for (int p = 0; p < 9; p++) acc[p] = 0.f;
        for (int d = 0; d < Dd; d++){
            float w1 = W1[d*256 + j];
            #pragma unroll
            for (int p = 0; p < 8; p++) acc[p] += sWp[p*Dd + d]*w1;
            acc[8] += sbp[d]*w1;
        }
        #pragma unroll
        for (int p = 0; p < 9; p++) g_wf[p*256 + j] = acc[p];
        return;
    }
    __shared__ int sawF, sawB;
    __shared__ int wtot[8];
    __shared__ int wbase[9];
    if (tid == 0){ sawF = 0; sawB = 0; }
    __syncthreads();
    for (int i = tid; i < Bb*Nn; i += 256){
        unsigned char c = mp[i];
        if (c == 0x3f || c == 0x80) sawF = 1;
        else if (c != 0 && (i & 3) != 0) sawB = 1;
    }
    __syncthreads();
    int mode = sawF ? 0 : (sawB ? 2 : 1);
    int b = blockIdx.x;
    int i = b*Nn + tid;
    bool m;
    if (mode == 0)      m = ((const float*)mp)[i] != 0.0f;
    else if (mode == 1) m = ((const int*)mp)[i]   != 0;
    else                m = mp[i] != 0;
    g_maskf[i] = m ? 1.0f : 0.0f;
    unsigned bits = __ballot_sync(0xffffffffu, m);
    int w = tid >> 5, lane = tid & 31;
    int rank = __popc(bits & ((1u << lane) - 1u));
    if (lane == 0) wtot[w] = __popc(bits);
    __syncthreads();
    if (tid == 0){
        int s = 0;
        #pragma unroll
        for (int ww = 0; ww < 8; ww++){ wbase[ww] = s; s += wtot[ww]; }
        wbase[8] = s;
        g_nobs[b] = s;
    }
    __syncthreads();
    int total = wbase[8];
    int obs_before = wbase[w] + rank;
    int pos = m ? obs_before : total + (tid - obs_before);
    g_obsidx[b*Nn + pos] = tid;
    if (tid < Dd) g_toksum[b*Dd + tid] = 0.f;
}

// ---- stage 1: h_mean for 16 tokens per block, fully packed f32x2 ----
__global__ __launch_bounds__(256) void kstage1(
    const float* __restrict__ x,
    const float* __restrict__ Wp,
    const float* __restrict__ bp,
    const float* __restrict__ W2){
    __shared__ __align__(16) u64 sxp[8][96];
    __shared__ float sxs[16][Pp];
    __shared__ __align__(16) u64 sG2[256][10];
    __shared__ u64 sv2[8][Dd];
    int tid = threadIdx.x;
    int bn0 = blockIdx.x*16;

    for (int idx = tid; idx < 8*Tt; idx += 256){
        int tp = idx/Tt, c = idx - tp*Tt;
        float lo = x[(bn0+2*tp  )*Tt + c] * g_maskf[bn0+2*tp];
        float hi = x[(bn0+2*tp+1)*Tt + c] * g_maskf[bn0+2*tp+1];
        u64 pk; PACK2(pk, lo, hi);
        sxp[tp][c] = pk;
    }
    __syncthreads();
    if (tid < 128){
        int t = tid >> 3, p = tid & 7;
        int tp = t >> 1, half = t & 1;
        float s = 0.f;
        #pragma unroll
        for (int l = 0; l < Ll; l++){
            u64 v = sxp[tp][l*Ss + p];
            s += half ? f2hi(v) : f2lo(v);
        }
        sxs[t][p] = s;
    }

    {
        int j = tid;
        u64 wf2[8];
        #pragma unroll
        for (int p = 0; p < 8; p++) PACKF2(wf2[p], g_wf[p*256 + j]);
        u64 ub2; PACKF2(ub2, g_wf[8*256 + j]);
        u64 C1P, C2P, HALFP;
        PACKF2(C1P, 0.035677408136f);
        PACKF2(C2P, 0.797884560803f);
        PACKF2(HALFP, 0.5f);
        #pragma unroll 1
        for (int tp = 0; tp < 8; tp++){
            const ulonglong2* xv = (const ulonglong2*)&sxp[tp][0];
            ulonglong2 A = xv[0], Bv = xv[1];
            u64 Gp = 0ull;
            #pragma unroll
            for (int l = 0; l < Ll; l++){
                ulonglong2 Cv = xv[2*l+2], Dv = xv[2*l+3];
                u64 u = ub2;
                FMA2(u, A.x,  wf2[0], u); FMA2(u, A.y,  wf2[1], u);
                FMA2(u, Bv.x, wf2[2], u); FMA2(u, Bv.y, wf2[3], u);
                FMA2(u, Cv.x, wf2[4], u); FMA2(u, Cv.y, wf2[5], u);
                FMA2(u, Dv.x, wf2[6], u); FMA2(u, Dv.y, wf2[7], u);
                u64 x2p; MUL2(x2p, u, u);
                u64 t1;  FMA2(t1, C1P, x2p, C2P);
                u64 zp;  MUL2(zp, u, t1);
                unsigned zl, zh; UNPACK2(zl, zh, zp);
                float tl = tanh_fast(__uint_as_float(zl));
                float th = tanh_fast(__uint_as_float(zh));
                u64 tpk; PACK2(tpk, tl, th);
                u64 hxp; MUL2(hxp, u, HALFP);
                u64 res; FMA2(res, hxp, tpk, hxp);
                ADD2(Gp, Gp, res);
                A = Cv; Bv = Dv;
            }
            sG2[j][tp] = Gp;
        }
    }
    __syncthreads();

    {
        int d = tid & 127, h2 = tid >> 7;
        u64 acc[8];
        #pragma unroll
        for (int tp = 0; tp < 8; tp++) acc[tp] = 0ull;
        int j0 = h2*128;
        for (int j = j0; j < j0+128; j++){
            float w = W2[j*Dd + d];
            u64 w2; PACKF2(w2, w);
            const ulonglong2* gr = (const ulonglong2*)&sG2[j][0];
            ulonglong2 g01 = gr[0], g23 = gr[1], g45 = gr[2], g67 = gr[3];
            FMA2(acc[0], g01.x, w2, acc[0]); FMA2(acc[1], g01.y, w2, acc[1]);
            FMA2(acc[2], g23.x, w2, acc[2]); FMA2(acc[3], g23.y, w2, acc[3]);
            FMA2(acc[4], g45.x, w2, acc[4]); FMA2(acc[5], g45.y, w2, acc[5]);
            FMA2(acc[6], g67.x, w2, acc[6]); FMA2(acc[7], g67.y, w2, acc[7]);
        }
        if (h2){
            #pragma unroll
            for (int tp = 0; tp < 8; tp++) sv2[tp][d] = acc[tp];
        }
        __syncthreads();
        if (!h2){
            float bpd = 23.0f*bp[d];
            float wpc[8];
            #pragma unroll
            for (int p = 0; p < 8; p++) wpc[p] = Wp[p*Dd + d];
            #pragma unroll
            for (int tp = 0; tp < 8; tp++){
                u64 o = sv2[tp][d];
                float lo = f2lo(acc[tp]) + f2lo(o);
                float hi = f2hi(acc[tp]) + f2hi(o);
                int t0 = 2*tp;
                float hs0 = bpd, hs1 = bpd;
                #pragma unroll
                for (int p = 0; p < 8; p++){
                    hs0 += sxs[t0  ][p]*wpc[p];
                    hs1 += sxs[t0+1][p]*wpc[p];
                }
                g_hmean[(bn0+t0  )*Dd + d] = (hs0 + lo) * (1.0f/23.0f);
                g_hmean[(bn0+t0+1)*Dd + d] = (hs1 + hi) * (1.0f/23.0f);
            }
        }
    }
}

// ---- q/k/v: 16 tokens/block, 192 threads = 3 proj x 64 column-pairs ----
__global__ __launch_bounds__(192, 4) void kqkv(
    const float* __restrict__ Wq,
    const float* __restrict__ Wk,
    const float* __restrict__ Wv,
    const float* __restrict__ ve){
    __shared__ __align__(16) float tokT[Dd][20];
    int tid = threadIdx.x;
    int b = blockIdx.x >> 4;
    int i0 = (blockIdx.x & 15) * 16;
    int n = g_nobs[b];
    for (int idx = tid; idx < 16*Dd; idx += 192){
        int t = idx >> 7, d = idx & 127;
        int i = i0 + t;
        float val = 0.f;
        if (i < n){
            int src = g_obsidx[b*Nn + i];
            val = g_hmean[(b*Nn + src)*Dd + d] + ve[src*Dd + d];
        }
        tokT[d][t] = val;
    }
    __syncthreads();
    if (tid < Dd){
        const float4* r = (const float4*)&tokT[tid][0];
        float4 a = r[0], b4 = r[1], c4 = r[2], d4 = r[3];
        float s = a.x+a.y+a.z+a.w + b4.x+b4.y+b4.z+b4.w
                + c4.x+c4.y+c4.z+c4.w + d4.x+d4.y+d4.z+d4.w;
        atomicAdd(&g_toksum[b*Dd + tid], s);
    }
    int which = tid >> 6;
    int c0 = (tid & 63) * 2;
    const float* W = (which == 0) ? Wq : (which == 1 ? Wk : Wv);
    float* dst = (which == 0) ? g_q : (which == 1 ? g_k : g_v);
    u64 a0[8], a1[8];
    #pragma unroll
    for (int r = 0; r < 8; r++){ a0[r] = 0ull; a1[r] = 0ull; }
    for (int d = 0; d < Dd; d++){
        float2 w = *(const float2*)&W[d*Dd + c0];
        u64 w2a, w2b;
        PACKF2(w2a, w.x);
        PACKF2(w2b, w.y);
        const ulonglong2* row = (const ulonglong2*)&tokT[d][0];
        ulonglong2 p0 = row[0], p1 = row[1], p2 = row[2], p3 = row[3];
        FMA2(a0[0], p0.x, w2a, a0[0]); FMA2(a1[0], p0.x, w2b, a1[0]);
        FMA2(a0[1], p0.y, w2a, a0[1]); FMA2(a1[1], p0.y, w2b, a1[1]);
        FMA2(a0[2], p1.x, w2a, a0[2]); FMA2(a1[2], p1.x, w2b, a1[2]);
        FMA2(a0[3], p1.y, w2a, a0[3]); FMA2(a1[3], p1.y, w2b, a1[3]);
        FMA2(a0[4], p2.x, w2a, a0[4]); FMA2(a1[4], p2.x, w2b, a1[4]);
        FMA2(a0[5], p2.y, w2a, a0[5]); FMA2(a1[5], p2.y, w2b, a1[5]);
        FMA2(a0[6], p3.x, w2a, a0[6]); FMA2(a1[6], p3.x, w2b, a1[6]);
        FMA2(a0[7], p3.y, w2a, a0[7]); FMA2(a1[7], p3.y, w2b, a1[7]);
    }
    #pragma unroll
    for (int r = 0; r < 8; r++){
        float2 e0 = make_float2(f2lo(a0[r]), f2lo(a1[r]));
        float2 e1 = make_float2(f2hi(a0[r]), f2hi(a1[r]));
        *(float2*)&dst[(b*Nn + i0 + 2*r    )*Dd + c0] = e0;
        *(float2*)&dst[(b*Nn + i0 + 2*r + 1)*Dd + c0] = e1;
    }
}

// ---- attention per (b,h): 2 queries/iter, q pre-packed in smem ----
__global__ __launch_bounds__(256) void kattn(){
    __shared__ __align__(16) float ks[Nn][20];    // K rows, conflict-free float4
    __shared__ __align__(16) u64 qp2[Nn/2][16];   // packed query pairs (broadcast reads)
    __shared__ float colsum[Nn];
    __shared__ float psum[16][17];
    int b = blockIdx.x >> 3, h = blockIdx.x & 7;
    int n = g_nobs[b];
    int tid = threadIdx.x;
    for (int idx = tid; idx < Nn*16; idx += 256){
        int jj = idx >> 4, c = idx & 15;
        ks[jj][c] = (jj < n) ? g_k[(b*Nn + jj)*Dd + h*16 + c] : 0.f;
    }
    for (int idx = tid; idx < (Nn/2)*16; idx += 256){
        int pr = idx >> 4, c = idx & 15;
        int i0 = pr*2;
        float q0 = (i0     < n) ? g_q[(b*Nn + i0    )*Dd + h*16 + c] : 0.f;
        float q1 = (i0 + 1 < n) ? g_q[(b*Nn + i0 + 1)*Dd + h*16 + c] : 0.f;
        u64 pk; PACK2(pk, q0, q1);
        qp2[pr][c] = pk;
    }
    for (int idx = tid; idx < Nn; idx += 256) colsum[idx] = 0.f;
    __syncthreads();
    int w = tid >> 5, lane = tid & 31;
    float cs[8];
    #pragma unroll
    for (int r = 0; r < 8; r++) cs[r] = 0.f;
    for (int pr = w; pr*2 < n; pr += 8){
        // broadcast-load packed q pair columns (8 LDS.128, all lanes same addr)
        u64 qp[16];
        const ulonglong2* qrow = (const ulonglong2*)&qp2[pr][0];
        #pragma unroll
        for (int c2 = 0; c2 < 8; c2++){
            ulonglong2 v = qrow[c2];
            qp[2*c2] = v.x; qp[2*c2+1] = v.y;
        }
        u64 s[8];
        #pragma unroll
        for (int r = 0; r < 8; r++){
            int jj = lane + 32*r;
            const float4* kr = (const float4*)&ks[jj][0];
            float4 k0 = kr[0], k1 = kr[1], k2 = kr[2], k3 = kr[3];
            u64 a = 0ull, kp;
            PACKF2(kp, k0.x); FMA2(a, qp[0],  kp, a);
            PACKF2(kp, k0.y); FMA2(a, qp[1],  kp, a);
            PACKF2(kp, k0.z); FMA2(a, qp[2],  kp, a);
            PACKF2(kp, k0.w); FMA2(a, qp[3],  kp, a);
            PACKF2(kp, k1.x); FMA2(a, qp[4],  kp, a);
            PACKF2(kp, k1.y); FMA2(a, qp[5],  kp, a);
            PACKF2(kp, k1.z); FMA2(a, qp[6],  kp, a);
            PACKF2(kp, k1.w); FMA2(a, qp[7],  kp, a);
            PACKF2(kp, k2.x); FMA2(a, qp[8],  kp, a);
            PACKF2(kp, k2.y); FMA2(a, qp[9],  kp, a);
            PACKF2(kp, k2.z); FMA2(a, qp[10], kp, a);
            PACKF2(kp, k2.w); FMA2(a, qp[11], kp, a);
            PACKF2(kp, k3.x); FMA2(a, qp[12], kp, a);
            PACKF2(kp, k3.y); FMA2(a, qp[13], kp, a);
            PACKF2(kp, k3.z); FMA2(a, qp[14], kp, a);
            PACKF2(kp, k3.w); FMA2(a, qp[15], kp, a);
            s[r] = a;
        }
        // softmax per query, accumulate colsum contributions
        #pragma unroll
        for (int qi = 0; qi < 2; qi++){
            float sq[8];
            #pragma unroll
            for (int r = 0; r < 8; r++){
                float raw = qi ? f2hi(s[r]) : f2lo(s[r]);
                int jj = lane + 32*r;
                sq[r] = (jj < n) ? raw*0.25f : -1e30f;
            }
            float mx = sq[0];
            #pragma unroll
            for (int r = 1; r < 8; r++) mx = fmaxf(mx, sq[r]);
            #pragma unroll
            for (int off = 16; off; off >>= 1) mx = fmaxf(mx, __shfl_xor_sync(0xffffffffu, mx, off));
            float se = 0.f;
            #pragma unroll
            for (int r = 0; r < 8; r++){
                sq[r] = __expf(sq[r] - mx);
                se += sq[r];
            }
            #pragma unroll
            for (int off = 16; off; off >>= 1) se += __shfl_xor_sync(0xffffffffu, se, off);
            float inv = (pr*2 + qi < n) ? __fdividef(1.0f, se) : 0.f;
            #pragma unroll
            for (int r = 0; r < 8; r++) cs[r] += sq[r]*inv;
        }
    }
    #pragma unroll
    for (int r = 0; r < 8; r++){
        int jj = lane + 32*r;
        atomicAdd(&colsum[jj], cs[r]);
    }
    __syncthreads();
    {
        int c = tid & 15, g = tid >> 4;
        float acc = 0.f;
        for (int j = g; j < n; j += 16)
            acc += colsum[j] * g_v[(b*Nn + j)*Dd + h*16 + c];
        psum[g][c] = acc;
        __syncthreads();
        if (tid < 16){
            float s = 0.f;
            #pragma unroll
            for (int gg = 0; gg < 16; gg++) s += psum[gg][tid];
            g_attnsum[b*Dd + h*16 + tid] = s;
        }
    }
}

// ---- per-batch epilogue: Q_sub, w_sub, conf, alpha*fill ----
__global__ __launch_bounds__(128) void kfinal(
    const float* __restrict__ Wo,
    const float* __restrict__ C,
    const float* __restrict__ Wdec,
    float* __restrict__ outQ,
    float* __restrict__ outW,
    float* __restrict__ outC){
    __shared__ float sa[Dd], Qs[Dd], lg[Kk], wk[Kk], zc[Dd];
    __shared__ float s_alpha, s_conf;
    int b = blockIdx.x, d = threadIdx.x;
    int n = g_nobs[b];
    sa[d] = g_attnsum[b*Dd + d];
    __syncthreads();
    float q = 0.f;
    #pragma unroll 4
    for (int jj = 0; jj < Dd; jj++) q += sa[jj]*Wo[jj*Dd + d];
    q = (q + g_toksum[b*Dd + d])/(float)n;
    Qs[d] = q;
    __syncthreads();
    if (d < Kk){
        float lgv = 0.f;
        #pragma unroll 4
        for (int dd = 0; dd < Dd; dd++) lgv += Qs[dd]*C[d*Dd + dd];
        lg[d] = lgv * 2.0f;
    }
    __syncthreads();
    if (d == 0){
        float mx = -1e30f;
        for (int k = 0; k < Kk; k++) mx = fmaxf(mx, lg[k]);
        float s = 0.f;
        for (int k = 0; k < Kk; k++){ wk[k] = expf(lg[k]-mx); s += wk[k]; }
        float inv = 1.0f/s, wmax = 0.f;
        for (int k = 0; k < Kk; k++){ wk[k] *= inv; wmax = fmaxf(wmax, wk[k]); }
        float conf = wmax * ((float)n/(float)Nn);
        s_conf = conf;
        s_alpha = 0.1f + 0.9f*conf;
        if (outC) outC[b] = conf;
    }
    __syncthreads();
    float z = 0.f;
    #pragma unroll
    for (int k = 0; k < Kk; k++) z += wk[k]*C[k*Dd + d];
    zc[d] = z;
    __syncthreads();
    float f = 0.f;
    #pragma unroll 4
    for (int jj = 0; jj < Dd; jj++) f += zc[jj]*Wdec[jj*Dd + d];
    g_afill[b*Dd + d] = s_alpha * f;
    if (outQ) outQ[b*Dd + d] = q;
    if (outW && d < Kk) outW[b*Kk + d] = wk[d];
}

// ---- y_hat, 8 tokens per block ----
__global__ __launch_bounds__(256) void kyhat(
    const float* __restrict__ Wh,
    float* __restrict__ y){
    __shared__ __align__(16) float E[8][Dd];
    __shared__ __align__(16) float sWhT[PLl][132];
    int tid = threadIdx.x;
    int bn0 = blockIdx.x*8;
    int b = bn0 >> 8;
    for (int idx = tid; idx < 8*Dd; idx += 256){
        int t = idx >> 7, d = idx & 127;
        float m = g_maskf[bn0+t];
        E[t][d] = g_hmean[(bn0+t)*Dd + d] + (1.0f - m)*g_afill[b*Dd + d];
    }
    for (int idx = tid; idx < Dd*PLl; idx += 256){
        int d = idx / PLl, pl = idx - d*PLl;
        sWhT[pl][d] = Wh[idx];
    }
    __syncthreads();
    if (tid < 192){
        int t = tid / PLl, pl = tid - t*PLl;
        float acc = 0.f;
        const float4* ev = (const float4*)&E[t][0];
        const float4* wv = (const float4*)&sWhT[pl][0];
        #pragma unroll 8
        for (int d4 = 0; d4 < Dd/4; d4++){
            float4 e = ev[d4], w = wv[d4];
            acc += e.x*w.x + e.y*w.y + e.z*w.z + e.w*w.w;
        }
        y[(bn0+t)*PLl + pl] = acc;
    }
}

extern "C" void kernel_launch(void* const* d_in, const int* in_sizes, int n_in,
                              void* d_out, int out_size){
    const float* x    = (const float*)d_in[0];
    const void*  mask = d_in[1];
    const float* Wp   = (const float*)d_in[2];
    const float* bp   = (const float*)d_in[3];
    const float* W1   = (const float*)d_in[4];
    const float* W2   = (const float*)d_in[5];
    const float* ve   = (const float*)d_in[6];
    const float* Wq   = (const float*)d_in[7];
    const float* Wk   = (const float*)d_in[8];
    const float* Wv   = (const float*)d_in[9];
    const float* Wo   = (const float*)d_in[10];
    const float* C    = (const float*)d_in[11];
    const float* Wdec = (const float*)d_in[12];
    const float* Wh   = (const float*)d_in[13];

    float* out = (float*)d_out;
    const int SZ_Y = Bb*Nn*PLl;
    const int SZ_Q = Bb*Dd;
    const int SZ_W = Bb*Kk;
    float* oy = out;
    float* oq = (out_size >= SZ_Y + SZ_Q)              ? out + SZ_Y                : nullptr;
    float* ow = (out_size >= SZ_Y + SZ_Q + SZ_W)       ? out + SZ_Y + SZ_Q         : nullptr;
    float* oc = (out_size >= SZ_Y + SZ_Q + SZ_W + Bb)  ? out + SZ_Y + SZ_Q + SZ_W  : nullptr;

    kmaskfold<<<Bb+1, 256>>>((const unsigned char*)mask, Wp, bp, W1);
    kstage1<<<Bb*Nn/16, 256>>>(x, Wp, bp, W2);
    kqkv<<<Bb*Nn/16, 192>>>(Wq, Wk, Wv, ve);
    kattn<<<Bb*Hh, 256>>>();
    kfinal<<<Bb, Dd>>>(Wo, C, Wdec, oq, ow, oc);
    kyhat<<<Bb*Nn/8, 256>>>(Wh, oy);
}

// round 12
// speedup vs baseline: 5.0284x; 1.1244x over previous
#include <cuda_runtime.h>
#include <math.h>

// ---- problem constants ----
#define Bb 64
#define Nn 256
#define Tt 96
#define Pp 8
#define Ss 4
#define Dd 128
#define Hh 8
#define Kk 16
#define PLl 24
#define Ll 23

// ---- scratch ----
__device__ float g_maskf[Bb*Nn];
__device__ float g_wf[9*256];          // rows 0..7: (Wp@W1)[p][j]; row 8: bp@W1
__device__ __align__(16) float g_hmean[Bb*Nn*Dd];
__device__ int   g_obsidx[Bb*Nn];
__device__ int   g_nobs[Bb];
__device__ __align__(16) float g_q[Bb*Nn*Dd];
__device__ __align__(16) float g_k[Bb*Nn*Dd];
__device__ __align__(16) float g_v[Bb*Nn*Dd];
__device__ float g_attnsum[Bb*Dd];
__device__ float g_toksum[Bb*Dd];
__device__ float g_afill[Bb*Dd];

typedef unsigned long long u64;

#define FMA2(d,a,b,c) asm("fma.rn.f32x2 %0, %1, %2, %3;" : "=l"(d) : "l"(a), "l"(b), "l"(c))
#define MUL2(d,a,b)   asm("mul.rn.f32x2 %0, %1, %2;" : "=l"(d) : "l"(a), "l"(b))
#define ADD2(d,a,b)   asm("add.rn.f32x2 %0, %1, %2;" : "=l"(d) : "l"(a), "l"(b))
#define PACKF2(o,f)   asm("mov.b64 %0, {%1, %1};" : "=l"(o) : "r"(__float_as_uint(f)))
#define PACK2(o,a,b)  asm("mov.b64 %0, {%1, %2};" : "=l"(o) : "r"(__float_as_uint(a)), "r"(__float_as_uint(b)))
#define UNPACK2(a,b,i) asm("mov.b64 {%0, %1}, %2;" : "=r"(a), "=r"(b) : "l"(i))

__device__ __forceinline__ float f2lo(u64 v){ return __uint_as_float((unsigned)(v & 0xffffffffull)); }
__device__ __forceinline__ float f2hi(u64 v){ return __uint_as_float((unsigned)(v >> 32)); }

__device__ __forceinline__ float tanh_fast(float z){
    float t;
    asm("tanh.approx.f32 %0, %1;" : "=f"(t) : "f"(z));
    return t;
}

// ---- fused: blocks 0..63 = mask decode + compaction (per-block dtype sniff);
//             block 64 = fold Wp/bp into W1 ----
__global__ __launch_bounds__(256) void kmaskfold(const unsigned char* __restrict__ mp,
                                                 const float* __restrict__ Wp,
                                                 const float* __restrict__ bp,
                                                 const float* __restrict__ W1){
    int tid = threadIdx.x;
    if (blockIdx.x == Bb){
        __shared__ float sWp[Pp*Dd];
        __shared__ float sbp[Dd];
        for (int i = tid; i < Pp*Dd; i += 256) sWp[i] = Wp[i];
        if (tid < Dd) sbp[tid] = bp[tid];
        __syncthreads();
        int j = tid;
        float acc[9];
        #pragma unroll
        for (int p = 0; p < 9; p++) acc[p] = 0.f;
        for (int d = 0; d < Dd; d++){
            float w1 = W1[d*256 + j];
            #pragma unroll
            for (int p = 0; p < 8; p++) acc[p] += sWp[p*Dd + d]*w1;
            acc[8] += sbp[d]*w1;
        }
        #pragma unroll
        for (int p = 0; p < 9; p++) g_wf[p*256 + j] = acc[p];
        return;
    }
    __shared__ int sawF, sawB;
    __shared__ int wtot[8];
    __shared__ int wbase[9];
    if (tid == 0){ sawF = 0; sawB = 0; }
    __syncthreads();
    for (int i = tid; i < Bb*Nn; i += 256){
        unsigned char c = mp[i];
        if (c == 0x3f || c == 0x80) sawF = 1;
        else if (c != 0 && (i & 3) != 0) sawB = 1;
    }
    __syncthreads();
    int mode = sawF ? 0 : (sawB ? 2 : 1);
    int b = blockIdx.x;
    int i = b*Nn + tid;
    bool m;
    if (mode == 0)      m = ((const float*)mp)[i] != 0.0f;
    else if (mode == 1) m = ((const int*)mp)[i]   != 0;
    else                m = mp[i] != 0;
    g_maskf[i] = m ? 1.0f : 0.0f;
    unsigned bits = __ballot_sync(0xffffffffu, m);
    int w = tid >> 5, lane = tid & 31;
    int rank = __popc(bits & ((1u << lane) - 1u));
    if (lane == 0) wtot[w] = __popc(bits);
    __syncthreads();
    if (tid == 0){
        int s = 0;
        #pragma unroll
        for (int ww = 0; ww < 8; ww++){ wbase[ww] = s; s += wtot[ww]; }
        wbase[8] = s;
        g_nobs[b] = s;
    }
    __syncthreads();
    int total = wbase[8];
    int obs_before = wbase[w] + rank;
    int pos = m ? obs_before : total + (tid - obs_before);
    g_obsidx[b*Nn + pos] = tid;
    if (tid < Dd) g_toksum[b*Dd + tid] = 0.f;
}

// ---- stage 1: h_mean for 16 tokens per block, fully packed f32x2 ----
__global__ __launch_bounds__(256) void kstage1(
    const float* __restrict__ x,
    const float* __restrict__ Wp,
    const float* __restrict__ bp,
    const float* __restrict__ W2){
    __shared__ __align__(16) u64 sxp[8][96];
    __shared__ float sxs[16][Pp];
    __shared__ __align__(16) u64 sG2[256][10];
    __shared__ u64 sv2[8][Dd];
    int tid = threadIdx.x;
    int bn0 = blockIdx.x*16;

    for (int idx = tid; idx < 8*Tt; idx += 256){
        int tp = idx/Tt, c = idx - tp*Tt;
        float lo = x[(bn0+2*tp  )*Tt + c] * g_maskf[bn0+2*tp];
        float hi = x[(bn0+2*tp+1)*Tt + c] * g_maskf[bn0+2*tp+1];
        u64 pk; PACK2(pk, lo, hi);
        sxp[tp][c] = pk;
    }
    __syncthreads();
    if (tid < 128){
        int t = tid >> 3, p = tid & 7;
        int tp = t >> 1, half = t & 1;
        float s = 0.f;
        #pragma unroll
        for (int l = 0; l < Ll; l++){
            u64 v = sxp[tp][l*Ss + p];
            s += half ? f2hi(v) : f2lo(v);
        }
        sxs[t][p] = s;
    }

    {
        int j = tid;
        u64 wf2[8];
        #pragma unroll
        for (int p = 0; p < 8; p++) PACKF2(wf2[p], g_wf[p*256 + j]);
        u64 ub2; PACKF2(ub2, g_wf[8*256 + j]);
        u64 C1P, C2P, HALFP;
        PACKF2(C1P, 0.035677408136f);
        PACKF2(C2P, 0.797884560803f);
        PACKF2(HALFP, 0.5f);
        #pragma unroll 1
        for (int tp = 0; tp < 8; tp++){
            const ulonglong2* xv = (const ulonglong2*)&sxp[tp][0];
            ulonglong2 A = xv[0], Bv = xv[1];
            u64 Gp = 0ull;
            #pragma unroll
            for (int l = 0; l < Ll; l++){
                ulonglong2 Cv = xv[2*l+2], Dv = xv[2*l+3];
                u64 u = ub2;
                FMA2(u, A.x,  wf2[0], u); FMA2(u, A.y,  wf2[1], u);
                FMA2(u, Bv.x, wf2[2], u); FMA2(u, Bv.y, wf2[3], u);
                FMA2(u, Cv.x, wf2[4], u); FMA2(u, Cv.y, wf2[5], u);
                FMA2(u, Dv.x, wf2[6], u); FMA2(u, Dv.y, wf2[7], u);
                u64 x2p; MUL2(x2p, u, u);
                u64 t1;  FMA2(t1, C1P, x2p, C2P);
                u64 zp;  MUL2(zp, u, t1);
                unsigned zl, zh; UNPACK2(zl, zh, zp);
                float tl = tanh_fast(__uint_as_float(zl));
                float th = tanh_fast(__uint_as_float(zh));
                u64 tpk; PACK2(tpk, tl, th);
                u64 hxp; MUL2(hxp, u, HALFP);
                u64 res; FMA2(res, hxp, tpk, hxp);
                ADD2(Gp, Gp, res);
                A = Cv; Bv = Dv;
            }
            sG2[j][tp] = Gp;
        }
    }
    __syncthreads();

    {
        int d = tid & 127, h2 = tid >> 7;
        u64 acc[8];
        #pragma unroll
        for (int tp = 0; tp < 8; tp++) acc[tp] = 0ull;
        int j0 = h2*128;
        for (int j = j0; j < j0+128; j++){
            float w = W2[j*Dd + d];
            u64 w2; PACKF2(w2, w);
            const ulonglong2* gr = (const ulonglong2*)&sG2[j][0];
            ulonglong2 g01 = gr[0], g23 = gr[1], g45 = gr[2], g67 = gr[3];
            FMA2(acc[0], g01.x, w2, acc[0]); FMA2(acc[1], g01.y, w2, acc[1]);
            FMA2(acc[2], g23.x, w2, acc[2]); FMA2(acc[3], g23.y, w2, acc[3]);
            FMA2(acc[4], g45.x, w2, acc[4]); FMA2(acc[5], g45.y, w2, acc[5]);
            FMA2(acc[6], g67.x, w2, acc[6]); FMA2(acc[7], g67.y, w2, acc[7]);
        }
        if (h2){
            #pragma unroll
            for (int tp = 0; tp < 8; tp++) sv2[tp][d] = acc[tp];
        }
        __syncthreads();
        if (!h2){
            float bpd = 23.0f*bp[d];
            float wpc[8];
            #pragma unroll
            for (int p = 0; p < 8; p++) wpc[p] = Wp[p*Dd + d];
            #pragma unroll
            for (int tp = 0; tp < 8; tp++){
                u64 o = sv2[tp][d];
                float lo = f2lo(acc[tp]) + f2lo(o);
                float hi = f2hi(acc[tp]) + f2hi(o);
                int t0 = 2*tp;
                float hs0 = bpd, hs1 = bpd;
                #pragma unroll
                for (int p = 0; p < 8; p++){
                    hs0 += sxs[t0  ][p]*wpc[p];
                    hs1 += sxs[t0+1][p]*wpc[p];
                }
                g_hmean[(bn0+t0  )*Dd + d] = (hs0 + lo) * (1.0f/23.0f);
                g_hmean[(bn0+t0+1)*Dd + d] = (hs1 + hi) * (1.0f/23.0f);
            }
        }
    }
}

// ---- q/k/v: 16 tokens/block, 192 threads = 3 proj x 64 column-pairs ----
__global__ __launch_bounds__(192, 4) void kqkv(
    const float* __restrict__ Wq,
    const float* __restrict__ Wk,
    const float* __restrict__ Wv,
    const float* __restrict__ ve){
    __shared__ __align__(16) float tokT[Dd][20];
    int tid = threadIdx.x;
    int b = blockIdx.x >> 4;
    int i0 = (blockIdx.x & 15) * 16;
    int n = g_nobs[b];
    for (int idx = tid; idx < 16*Dd; idx += 192){
        int t = idx >> 7, d = idx & 127;
        int i = i0 + t;
        float val = 0.f;
        if (i < n){
            int src = g_obsidx[b*Nn + i];
            val = g_hmean[(b*Nn + src)*Dd + d] + ve[src*Dd + d];
        }
        tokT[d][t] = val;
    }
    __syncthreads();
    if (tid < Dd){
        const float4* r = (const float4*)&tokT[tid][0];
        float4 a = r[0], b4 = r[1], c4 = r[2], d4 = r[3];
        float s = a.x+a.y+a.z+a.w + b4.x+b4.y+b4.z+b4.w
                + c4.x+c4.y+c4.z+c4.w + d4.x+d4.y+d4.z+d4.w;
        atomicAdd(&g_toksum[b*Dd + tid], s);
    }
    int which = tid >> 6;
    int c0 = (tid & 63) * 2;
    const float* W = (which == 0) ? Wq : (which == 1 ? Wk : Wv);
    float* dst = (which == 0) ? g_q : (which == 1 ? g_k : g_v);
    u64 a0[8], a1[8];
    #pragma unroll
    for (int r = 0; r < 8; r++){ a0[r] = 0ull; a1[r] = 0ull; }
    for (int d = 0; d < Dd; d++){
        float2 w = *(const float2*)&W[d*Dd + c0];
        u64 w2a, w2b;
        PACKF2(w2a, w.x);
        PACKF2(w2b, w.y);
        const ulonglong2* row = (const ulonglong2*)&tokT[d][0];
        ulonglong2 p0 = row[0], p1 = row[1], p2 = row[2], p3 = row[3];
        FMA2(a0[0], p0.x, w2a, a0[0]); FMA2(a1[0], p0.x, w2b, a1[0]);
        FMA2(a0[1], p0.y, w2a, a0[1]); FMA2(a1[1], p0.y, w2b, a1[1]);
        FMA2(a0[2], p1.x, w2a, a0[2]); FMA2(a1[2], p1.x, w2b, a1[2]);
        FMA2(a0[3], p1.y, w2a, a0[3]); FMA2(a1[3], p1.y, w2b, a1[3]);
        FMA2(a0[4], p2.x, w2a, a0[4]); FMA2(a1[4], p2.x, w2b, a1[4]);
        FMA2(a0[5], p2.y, w2a, a0[5]); FMA2(a1[5], p2.y, w2b, a1[5]);
        FMA2(a0[6], p3.x, w2a, a0[6]); FMA2(a1[6], p3.x, w2b, a1[6]);
        FMA2(a0[7], p3.y, w2a, a0[7]); FMA2(a1[7], p3.y, w2b, a1[7]);
    }
    #pragma unroll
    for (int r = 0; r < 8; r++){
        float2 e0 = make_float2(f2lo(a0[r]), f2lo(a1[r]));
        float2 e1 = make_float2(f2hi(a0[r]), f2hi(a1[r]));
        *(float2*)&dst[(b*Nn + i0 + 2*r    )*Dd + c0] = e0;
        *(float2*)&dst[(b*Nn + i0 + 2*r + 1)*Dd + c0] = e1;
    }
}

// ---- attention per (b,h): 2 queries/iter, scalar accumulators, shuffle-broadcast q ----
__global__ __launch_bounds__(256, 3) void kattn(){
    __shared__ __align__(16) float ks[Nn][20];   // K rows, conflict-free float4
    __shared__ float colsum[Nn];
    __shared__ float psum[16][17];
    int b = blockIdx.x >> 3, h = blockIdx.x & 7;
    int n = g_nobs[b];
    int tid = threadIdx.x;
    for (int idx = tid; idx < Nn*16; idx += 256){
        int jj = idx >> 4, c = idx & 15;
        ks[jj][c] = (jj < n) ? g_k[(b*Nn + jj)*Dd + h*16 + c] : 0.f;
    }
    for (int idx = tid; idx < Nn; idx += 256) colsum[idx] = 0.f;
    __syncthreads();
    int w = tid >> 5, lane = tid & 31;
    float cs[8];
    #pragma unroll
    for (int r = 0; r < 8; r++) cs[r] = 0.f;
    for (int i0 = w*2; i0 < n; i0 += 16){
        // lanes 0-15 carry q[i0], lanes 16-31 carry q[i0+1] (zero if invalid)
        float qv;
        if (lane < 16) qv = g_q[(b*Nn + i0)*Dd + h*16 + lane];
        else           qv = (i0 + 1 < n) ? g_q[(b*Nn + i0 + 1)*Dd + h*16 + (lane - 16)] : 0.f;
        float q0[16], q1[16];
        #pragma unroll
        for (int c = 0; c < 16; c++){
            q0[c] = __shfl_sync(0xffffffffu, qv, c);
            q1[c] = __shfl_sync(0xffffffffu, qv, 16 + c);
        }
        float sc0[8], sc1[8];
        #pragma unroll
        for (int r = 0; r < 8; r++){
            int jj = lane + 32*r;
            const float4* kr = (const float4*)&ks[jj][0];
            float4 k0 = kr[0], k1 = kr[1], k2 = kr[2], k3 = kr[3];
            float s0, s1;
            s0  = q0[0]*k0.x  + q0[1]*k0.y  + q0[2]*k0.z  + q0[3]*k0.w;
            s0 += q0[4]*k1.x  + q0[5]*k1.y  + q0[6]*k1.z  + q0[7]*k1.w;
            s0 += q0[8]*k2.x  + q0[9]*k2.y  + q0[10]*k2.z + q0[11]*k2.w;
            s0 += q0[12]*k3.x + q0[13]*k3.y + q0[14]*k3.z + q0[15]*k3.w;
            s1  = q1[0]*k0.x  + q1[1]*k0.y  + q1[2]*k0.z  + q1[3]*k0.w;
            s1 += q1[4]*k1.x  + q1[5]*k1.y  + q1[6]*k1.z  + q1[7]*k1.w;
            s1 += q1[8]*k2.x  + q1[9]*k2.y  + q1[10]*k2.z + q1[11]*k2.w;
            s1 += q1[12]*k3.x + q1[13]*k3.y + q1[14]*k3.z + q1[15]*k3.w;
            bool valid = (jj < n);
            sc0[r] = valid ? s0*0.25f : -1e30f;
            sc1[r] = valid ? s1*0.25f : -1e30f;
        }
        // softmax for query i0
        {
            float mx = sc0[0];
            #pragma unroll
            for (int r = 1; r < 8; r++) mx = fmaxf(mx, sc0[r]);
            #pragma unroll
            for (int off = 16; off; off >>= 1) mx = fmaxf(mx, __shfl_xor_sync(0xffffffffu, mx, off));
            float se = 0.f;
            #pragma unroll
            for (int r = 0; r < 8; r++){ sc0[r] = __expf(sc0[r] - mx); se += sc0[r]; }
            #pragma unroll
            for (int off = 16; off; off >>= 1) se += __shfl_xor_sync(0xffffffffu, se, off);
            float inv = __fdividef(1.0f, se);
            #pragma unroll
            for (int r = 0; r < 8; r++) cs[r] += sc0[r]*inv;
        }
        // softmax for query i0+1 (if valid)
        {
            float mx = sc1[0];
            #pragma unroll
            for (int r = 1; r < 8; r++) mx = fmaxf(mx, sc1[r]);
            #pragma unroll
            for (int off = 16; off; off >>= 1) mx = fmaxf(mx, __shfl_xor_sync(0xffffffffu, mx, off));
            float se = 0.f;
            #pragma unroll
            for (int r = 0; r < 8; r++){ sc1[r] = __expf(sc1[r] - mx); se += sc1[r]; }
            #pragma unroll
            for (int off = 16; off; off >>= 1) se += __shfl_xor_sync(0xffffffffu, se, off);
            float inv = (i0 + 1 < n) ? __fdividef(1.0f, se) : 0.f;
            #pragma unroll
            for (int r = 0; r < 8; r++) cs[r] += sc1[r]*inv;
        }
    }
    #pragma unroll
    for (int r = 0; r < 8; r++){
        int jj = lane + 32*r;
        atomicAdd(&colsum[jj], cs[r]);
    }
    __syncthreads();
    {
        int c = tid & 15, g = tid >> 4;
        float acc = 0.f;
        for (int j = g; j < n; j += 16)
            acc += colsum[j] * g_v[(b*Nn + j)*Dd + h*16 + c];
        psum[g][c] = acc;
        __syncthreads();
        if (tid < 16){
            float s = 0.f;
            #pragma unroll
            for (int gg = 0; gg < 16; gg++) s += psum[gg][tid];
            g_attnsum[b*Dd + h*16 + tid] = s;
        }
    }
}

// ---- per-batch epilogue: Q_sub, w_sub, conf, alpha*fill ----
__global__ __launch_bounds__(128) void kfinal(
    const float* __restrict__ Wo,
    const float* __restrict__ C,
    const float* __restrict__ Wdec,
    float* __restrict__ outQ,
    float* __restrict__ outW,
    float* __restrict__ outC){
    __shared__ float sa[Dd], Qs[Dd], lg[Kk], wk[Kk], zc[Dd];
    __shared__ float s_alpha, s_conf;
    int b = blockIdx.x, d = threadIdx.x;
    int n = g_nobs[b];
    sa[d] = g_attnsum[b*Dd + d];
    __syncthreads();
    float q = 0.f;
    #pragma unroll 4
    for (int jj = 0; jj < Dd; jj++) q += sa[jj]*Wo[jj*Dd + d];
    q = (q + g_toksum[b*Dd + d])/(float)n;
    Qs[d] = q;
    __syncthreads();
    if (d < Kk){
        float lgv = 0.f;
        #pragma unroll 4
        for (int dd = 0; dd < Dd; dd++) lgv += Qs[dd]*C[d*Dd + dd];
        lg[d] = lgv * 2.0f;
    }
    __syncthreads();
    if (d == 0){
        float mx = -1e30f;
        for (int k = 0; k < Kk; k++) mx = fmaxf(mx, lg[k]);
        float s = 0.f;
        for (int k = 0; k < Kk; k++){ wk[k] = expf(lg[k]-mx); s += wk[k]; }
        float inv = 1.0f/s, wmax = 0.f;
        for (int k = 0; k < Kk; k++){ wk[k] *= inv; wmax = fmaxf(wmax, wk[k]); }
        float conf = wmax * ((float)n/(float)Nn);
        s_conf = conf;
        s_alpha = 0.1f + 0.9f*conf;
        if (outC) outC[b] = conf;
    }
    __syncthreads();
    float z = 0.f;
    #pragma unroll
    for (int k = 0; k < Kk; k++) z += wk[k]*C[k*Dd + d];
    zc[d] = z;
    __syncthreads();
    float f = 0.f;
    #pragma unroll 4
    for (int jj = 0; jj < Dd; jj++) f += zc[jj]*Wdec[jj*Dd + d];
    g_afill[b*Dd + d] = s_alpha * f;
    if (outQ) outQ[b*Dd + d] = q;
    if (outW && d < Kk) outW[b*Kk + d] = wk[d];
}

// ---- y_hat, 8 tokens per block ----
__global__ __launch_bounds__(256) void kyhat(
    const float* __restrict__ Wh,
    float* __restrict__ y){
    __shared__ __align__(16) float E[8][Dd];
    __shared__ __align__(16) float sWhT[PLl][132];
    int tid = threadIdx.x;
    int bn0 = blockIdx.x*8;
    int b = bn0 >> 8;
    for (int idx = tid; idx < 8*Dd; idx += 256){
        int t = idx >> 7, d = idx & 127;
        float m = g_maskf[bn0+t];
        E[t][d] = g_hmean[(bn0+t)*Dd + d] + (1.0f - m)*g_afill[b*Dd + d];
    }
    for (int idx = tid; idx < Dd*PLl; idx += 256){
        int d = idx / PLl, pl = idx - d*PLl;
        sWhT[pl][d] = Wh[idx];
    }
    __syncthreads();
    if (tid < 192){
        int t = tid / PLl, pl = tid - t*PLl;
        float acc = 0.f;
        const float4* ev = (const float4*)&E[t][0];
        const float4* wv = (const float4*)&sWhT[pl][0];
        #pragma unroll 8
        for (int d4 = 0; d4 < Dd/4; d4++){
            float4 e = ev[d4], w = wv[d4];
            acc += e.x*w.x + e.y*w.y + e.z*w.z + e.w*w.w;
        }
        y[(bn0+t)*PLl + pl] = acc;
    }
}

extern "C" void kernel_launch(void* const* d_in, const int* in_sizes, int n_in,
                              void* d_out, int out_size){
    const float* x    = (const float*)d_in[0];
    const void*  mask = d_in[1];
    const float* Wp   = (const float*)d_in[2];
    const float* bp   = (const float*)d_in[3];
    const float* W1   = (const float*)d_in[4];
    const float* W2   = (const float*)d_in[5];
    const float* ve   = (const float*)d_in[6];
    const float* Wq   = (const float*)d_in[7];
    const float* Wk   = (const float*)d_in[8];
    const float* Wv   = (const float*)d_in[9];
    const float* Wo   = (const float*)d_in[10];
    const float* C    = (const float*)d_in[11];
    const float* Wdec = (const float*)d_in[12];
    const float* Wh   = (const float*)d_in[13];

    float* out = (float*)d_out;
    const int SZ_Y = Bb*Nn*PLl;
    const int SZ_Q = Bb*Dd;
    const int SZ_W = Bb*Kk;
    float* oy = out;
    float* oq = (out_size >= SZ_Y + SZ_Q)              ? out + SZ_Y                : nullptr;
    float* ow = (out_size >= SZ_Y + SZ_Q + SZ_W)       ? out + SZ_Y + SZ_Q         : nullptr;
    float* oc = (out_size >= SZ_Y + SZ_Q + SZ_W + Bb)  ? out + SZ_Y + SZ_Q + SZ_W  : nullptr;

    kmaskfold<<<Bb+1, 256>>>((const unsigned char*)mask, Wp, bp, W1);
    kstage1<<<Bb*Nn/16, 256>>>(x, Wp, bp, W2);
    kqkv<<<Bb*Nn/16, 192>>>(Wq, Wk, Wv, ve);
    kattn<<<Bb*Hh, 256>>>();
    kfinal<<<Bb, Dd>>>(Wo, C, Wdec, oq, ow, oc);
    kyhat<<<Bb*Nn/8, 256>>>(Wh, oy);
}